// round 14
// baseline (speedup 1.0000x reference)
#include <cuda_runtime.h>
#include <cuda_bf16.h>
#include <cstdint>

#define DD 128
#define NTHREADS 544            // 16 consumer warps + 1 producer warp
#define NCONS 512

#if defined(__CUDA_ARCH__) && defined(__CUDA_ARCH_FEAT_SM103_ALL)
#define TC_OK 1
#else
#define TC_OK 0
#endif

// -------------------- device scratch (no allocations allowed) ---------------
__device__ float g_x2[4096];
__device__ float g_rx[4096];
__device__ float4 g_cc[32768];            // per-code {y2, 1/(1-y2), fb, 0}
__device__ __nv_bfloat16 g_phi[4096 * DD];
__device__ __nv_bfloat16 g_plo[4096 * DD];
__device__ __nv_bfloat16 g_yhi[32768 * DD];
__device__ __nv_bfloat16 g_ylo[32768 * DD];
__device__ unsigned g_barA;
__device__ unsigned g_barB;

// -------------------- small helpers ----------------------------------------
__device__ __forceinline__ float wsum(float v) {
    #pragma unroll
    for (int o = 16; o > 0; o >>= 1) v += __shfl_xor_sync(0xffffffffu, v, o);
    return v;
}

__device__ __forceinline__ uint32_t s2u(const void* p) {
    uint32_t a;
    asm("{ .reg .u64 t; cvta.to.shared.u64 t, %1; cvt.u32.u64 %0, t; }"
        : "=r"(a) : "l"(p));
    return a;
}

__device__ __forceinline__ void cpasync16(uint32_t dst, const void* src) {
    asm volatile("cp.async.cg.shared.global [%0], [%1], 16;" :: "r"(dst), "l"(src));
}

__device__ __forceinline__ void mbar_init(uint32_t a, uint32_t cnt) {
    asm volatile("mbarrier.init.shared.b64 [%0], %1;" :: "r"(a), "r"(cnt) : "memory");
}
// HW-sleep wait (suspend-time hint -> no issue-slot burn while waiting)
__device__ __forceinline__ void mbar_wait(uint32_t a, uint32_t parity) {
    asm volatile(
        "{\n\t.reg .pred P;\n"
        "W%=:\n\t"
        "mbarrier.try_wait.parity.acquire.cta.shared::cta.b64 P, [%0], %1, 0x989680;\n\t"
        "@!P bra W%=;\n\t}"
        :: "r"(a), "r"(parity) : "memory");
}
__device__ __forceinline__ void mbar_arrive(uint32_t a) {
    asm volatile("mbarrier.arrive.shared.b64 _, [%0];" :: "r"(a) : "memory");
}
__device__ __forceinline__ void cp_arrive(uint32_t a) {
    asm volatile("cp.async.mbarrier.arrive.noinc.shared.b64 [%0];"
                 :: "r"(a) : "memory");
}
__device__ __forceinline__ float sqrt_approx(float x) {
    float r;
    asm("sqrt.approx.f32 %0, %1;" : "=f"(r) : "f"(x));
    return r;
}

// -------------------- packed f32x2 ops (Blackwell) ---------------------------
__device__ __forceinline__ uint64_t pk2(float lo, float hi) {
    uint64_t r;
    asm("mov.b64 %0, {%1, %2};" : "=l"(r) : "f"(lo), "f"(hi));
    return r;
}
__device__ __forceinline__ void unpk2(uint64_t v, float& lo, float& hi) {
    asm("mov.b64 {%0, %1}, %2;" : "=f"(lo), "=f"(hi) : "l"(v));
}
__device__ __forceinline__ uint64_t add2(uint64_t a, uint64_t b) {
    uint64_t r; asm("add.rn.f32x2 %0, %1, %2;" : "=l"(r) : "l"(a), "l"(b)); return r;
}
__device__ __forceinline__ uint64_t mul2(uint64_t a, uint64_t b) {
    uint64_t r; asm("mul.rn.f32x2 %0, %1, %2;" : "=l"(r) : "l"(a), "l"(b)); return r;
}
__device__ __forceinline__ uint64_t fma2v(uint64_t a, uint64_t b, uint64_t c) {
    uint64_t r; asm("fma.rn.f32x2 %0, %1, %2, %3;" : "=l"(r) : "l"(a), "l"(b), "l"(c)); return r;
}

#if TC_OK
__device__ __forceinline__ void tm_alloc(uint32_t smem_res, uint32_t ncols) {
    asm volatile("tcgen05.alloc.cta_group::1.sync.aligned.shared::cta.b32 [%0], %1;"
                 :: "r"(smem_res), "r"(ncols) : "memory");
}
__device__ __forceinline__ void tm_dealloc(uint32_t tmem, uint32_t ncols) {
    asm volatile("tcgen05.dealloc.cta_group::1.sync.aligned.b32 %0, %1;" :: "r"(tmem), "r"(ncols));
}
__device__ __forceinline__ void tm_commit(uint32_t mbar) {
    asm volatile("tcgen05.commit.cta_group::1.mbarrier::arrive::one.shared::cluster.b64 [%0];"
                 :: "r"(mbar) : "memory");
}
__device__ __forceinline__ void tm_fence_after() {
    asm volatile("tcgen05.fence::after_thread_sync;" ::: "memory");
}
__device__ __forceinline__ void fence_async_shared() {
    asm volatile("fence.proxy.async.shared::cta;" ::: "memory");
}
__device__ __forceinline__ void tm_waitld() {
    asm volatile("tcgen05.wait::ld.sync.aligned;" ::: "memory");
}
__device__ __forceinline__ void ldtm16(uint32_t* r, uint32_t a) {
    asm volatile("tcgen05.ld.sync.aligned.32x32b.x16.b32 "
                 "{%0,%1,%2,%3,%4,%5,%6,%7,%8,%9,%10,%11,%12,%13,%14,%15}, [%16];"
                 : "=r"(r[0]), "=r"(r[1]), "=r"(r[2]),  "=r"(r[3]),
                   "=r"(r[4]), "=r"(r[5]), "=r"(r[6]),  "=r"(r[7]),
                   "=r"(r[8]), "=r"(r[9]), "=r"(r[10]), "=r"(r[11]),
                   "=r"(r[12]), "=r"(r[13]), "=r"(r[14]), "=r"(r[15])
                 : "r"(a));
}

// SS bf16 MMA, cg1, fp32 accumulate. M=128, N=128.
#define IDESC_BF16_128x128 ((1u<<4)|(1u<<7)|(1u<<10)|((128u/8u)<<17)|((128u/16u)<<24))

__device__ __forceinline__ void mma_ss(uint32_t d, uint64_t a, uint64_t b,
                                       uint32_t en) {
    asm volatile(
        "{\n\t.reg .pred p;\n\t"
        "setp.ne.u32 p, %5, 0;\n\t"
        "tcgen05.mma.cta_group::1.kind::f16 [%0], %1, %2, %3, {%4, %4, %4, %4}, p;\n\t}"
        :: "r"(d), "l"(a), "l"(b), "r"(IDESC_BF16_128x128), "r"(0u), "r"(en)
        : "memory");
}
#endif  // TC_OK

// 64-bit SMEM descriptor: SW128, version 1 (Blackwell), SBO=64, LBO=1
__device__ __forceinline__ uint64_t mkdesc(uint32_t addr) {
    return ((uint64_t)2 << 61) | ((uint64_t)1 << 46) | ((uint64_t)64 << 32)
         | ((uint64_t)1 << 16) | (uint64_t)((addr >> 4) & 0x3FFFu);
}

// Atom-blocked SW128 offset for a 128-row x 128-col bf16 tile.
__device__ __forceinline__ uint32_t tile_off(int r, int g) {
    uint32_t lin = (uint32_t)((r >> 3) + ((g >> 3) << 4)) * 1024u
                 + (uint32_t)(r & 7) * 128u + (uint32_t)(g & 7) * 16u;
    return lin ^ ((lin >> 3) & 0x70u);
}

// -------------------- smem layout --------------------------------------------
#define SM_TMEMPTR 0
#define SM_MBAR    8                             // 10 mbars x 8B
#define SM_A       1024                          // P: hi 32KB + lo 32KB
#define SM_B       (SM_A + 65536)                // Y: 2 x (hi 32KB + lo 32KB); W^T in prep
#define SM_SXR     (SM_B + 131072)               // x2[128] floats, rx[128] floats
#define SM_TOTAL   (SM_SXR + 1024)

#define FULLB(s) (sb + SM_MBAR + (uint32_t)(s) * 8u)
#define EBB(s)   (sb + SM_MBAR + 32u + (uint32_t)(s) * 8u)
#define BFB(b)   (sb + SM_MBAR + 64u + (uint32_t)(b) * 8u)

#if TC_OK
// A = Y (sa_y), B = P (sb_p): D[code, row]
__device__ __forceinline__ void issue_tile(uint32_t sa_y, uint32_t sb_p, uint32_t d) {
    uint64_t ah = mkdesc(sa_y), al = mkdesc(sa_y + 32768u);
    uint64_t bh = mkdesc(sb_p), bl = mkdesc(sb_p + 32768u);
    #pragma unroll
    for (int kk = 0; kk < 8; kk++) {
        uint32_t off = (uint32_t)(kk >> 2) * 1024u + (uint32_t)(kk & 3) * 2u;
        mma_ss(d, ah + off, bh + off, kk > 0 ? 1u : 0u);
        mma_ss(d, ah + off, bl + off, 1u);
        mma_ss(d, al + off, bh + off, 1u);
    }
}

// packed epilogue for 8 element-pairs (16 rows) from one ldtm16 chunk.
template<int KC>
__device__ __forceinline__ void epi_block(const uint32_t* __restrict__ r,
                                          const float* __restrict__ x2a,
                                          const float* __restrict__ rxa,
                                          int pbase,
                                          uint64_t qx2, uint64_t qy2,
                                          float qz, float c2,
                                          float* __restrict__ obase, int Krt) {
    const uint64_t NEG2  = pk2(-2.f, -2.f);
    const uint64_t ONE2  = pk2(1.f, 1.f);
    const uint64_t MONE2 = pk2(-1.f, -1.f);
    #pragma unroll
    for (int p = 0; p < 8; p++) {
        const int pp = pbase + p;
        float2 x2p = *(const float2*)(x2a + 2 * pp);
        float2 rxp = *(const float2*)(rxa + 2 * pp);
        uint64_t xv2 = pk2(__uint_as_float(r[2 * p]), __uint_as_float(r[2 * p + 1]));
        uint64_t s2  = add2(pk2(x2p.x, x2p.y), qx2);
        uint64_t u2  = fma2v(xv2, NEG2, s2);
        float u0, u1; unpk2(u2, u0, u1);
        u0 = fmaxf(u0, 0.f); u1 = fmaxf(u1, 0.f);
        uint64_t rr2 = mul2(pk2(rxp.x, rxp.y), qy2);
        uint64_t t2  = fma2v(pk2(u0, u1), rr2, ONE2);
        uint64_t a2  = fma2v(t2, t2, MONE2);
        float t0, t1; unpk2(t2, t0, t1);
        float a0, a1; unpk2(a2, a0, a1);
        float w0 = sqrt_approx(a0), w1 = sqrt_approx(a1);
        float l0 = __log2f(t0 + w0), l1 = __log2f(t1 + w1);
        float res0 = fmaf(l0 * l0, c2, qz);
        float res1 = fmaf(l1 * l1, c2, qz);
        if (KC > 0) {
            __stcs(obase + (size_t)(2 * pp) * KC, res0);
            __stcs(obase + (size_t)(2 * pp + 1) * KC, res1);
        } else {
            __stcs(obase + (size_t)(2 * pp) * Krt, res0);
            __stcs(obase + (size_t)(2 * pp + 1) * Krt, res1);
        }
    }
}
#endif

__device__ __forceinline__ float hd_logit(float xv, float x2r, float rxr,
                                          float y2c, float ryc, float fbc,
                                          float nit2) {
    float u = fmaxf(fmaf(-2.f, xv, x2r + y2c), 0.f);
    float t = fmaf(u, rxr * ryc, 1.f);
    float a = fmaf(t, t, -1.f);
    float w = sqrt_approx(a);
    float l = __logf(t + w);
    return fmaf(l * l, nit2, fbc);
}

__device__ __forceinline__ uint32_t pack_bf16(float a, float b) {
    __nv_bfloat16 ha = __float2bfloat16_rn(a), hb = __float2bfloat16_rn(b);
    uint16_t ua = *(uint16_t*)&ha, ub = *(uint16_t*)&hb;
    return (uint32_t)ua | ((uint32_t)ub << 16);
}

// ======================= the single fused kernel =============================
__global__ void __launch_bounds__(NTHREADS, 1)
hd_fused(const float* __restrict__ V, const float* __restrict__ Y,
         const float* __restrict__ W, const float* __restrict__ bvec,
         const float* __restrict__ fb, const float* __restrict__ temp,
         float* __restrict__ out, int NROW, int K) {
    extern __shared__ char smem[];
    uint32_t sb = s2u(smem);
    int tid = threadIdx.x, w = tid >> 5, lane = tid & 31;

    // =================== phase 0: prep (rows + codes) =======================
    {
        const int nrowblk = (NROW + 15) >> 4;        // 16 rows per block
        if ((int)blockIdx.x < nrowblk) {
            float* sWt = (float*)(smem + SM_B);
            for (int idx = tid; idx < DD * DD; idx += NTHREADS) {
                int d = idx >> 7, e = idx & 127;
                sWt[e * 132 + d] = W[idx];
            }
            __syncthreads();
            int row = ((int)blockIdx.x << 4) + w;
            if (w < 16 && row < NROW) {
                const float* v = V + (size_t)row * DD;
                float vq[4];
                #pragma unroll
                for (int q = 0; q < 4; q++) vq[q] = v[lane + 32 * q];
                float n2 = wsum(vq[0]*vq[0] + vq[1]*vq[1] + vq[2]*vq[2] + vq[3]*vq[3]);
                float n  = sqrtf(fmaxf(n2, 1e-30f));
                float xn = tanhf(n);
                float s0 = xn / n;
                float p0[4];
                #pragma unroll
                for (int q = 0; q < 4; q++) p0[q] = s0 * vq[q];

                float mq[4] = {0.f, 0.f, 0.f, 0.f};
                #pragma unroll
                for (int e = 0; e < DD; e++) {
                    float pe = __shfl_sync(0xffffffffu, p0[e >> 5], e & 31);
                    #pragma unroll
                    for (int q = 0; q < 4; q++)
                        mq[q] = fmaf(pe, sWt[e * 132 + 32 * q + lane], mq[q]);
                }
                float mxn2 = wsum(mq[0]*mq[0] + mq[1]*mq[1] + mq[2]*mq[2] + mq[3]*mq[3]);
                float mxn  = sqrtf(fmaxf(mxn2, 1e-30f));
                float xc   = fminf(xn, 1.f - 1e-5f);
                float ath  = 0.5f * __logf((1.f + xc) / (1.f - xc));
                float g    = tanhf(mxn / fmaxf(xn, 1e-15f) * ath) / mxn;
                float rq[4];
                #pragma unroll
                for (int q = 0; q < 4; q++) rq[q] = g * mq[q];

                float bq[4];
                #pragma unroll
                for (int q = 0; q < 4; q++) bq[q] = bvec[lane + 32 * q];
                float bn2 = wsum(bq[0]*bq[0] + bq[1]*bq[1] + bq[2]*bq[2] + bq[3]*bq[3]);
                float bn  = sqrtf(fmaxf(bn2, 1e-30f));
                float tb  = tanhf(bn);
                float sb2 = tb / bn;
                float ebq[4];
                #pragma unroll
                for (int q = 0; q < 4; q++) ebq[q] = sb2 * bq[q];
                float y2 = tb * tb;

                float x2 = wsum(rq[0]*rq[0] + rq[1]*rq[1] + rq[2]*rq[2] + rq[3]*rq[3]);
                float xy = wsum(rq[0]*ebq[0] + rq[1]*ebq[1] + rq[2]*ebq[2] + rq[3]*ebq[3]);
                float ca  = 1.f + 2.f * xy + y2;
                float cb  = 1.f - x2;
                float den = fmaxf(1.f + 2.f * xy + x2 * y2, 1e-15f);
                float inv = 1.f / den;
                float pq[4], ps = 0.f;
                #pragma unroll
                for (int q = 0; q < 4; q++) {
                    pq[q] = (ca * rq[q] + cb * ebq[q]) * inv;
                    ps = fmaf(pq[q], pq[q], ps);
                }
                float px2 = wsum(ps);
                #pragma unroll
                for (int q = 0; q < 4; q++) {
                    int d = lane + 32 * q;
                    __nv_bfloat16 hi = __float2bfloat16_rn(pq[q]);
                    __nv_bfloat16 lo = __float2bfloat16_rn(pq[q] - __bfloat162float(hi));
                    g_phi[(size_t)row * DD + d] = hi;
                    g_plo[(size_t)row * DD + d] = lo;
                }
                if (lane == 0) {
                    g_x2[row] = px2;
                    g_rx[row] = 2.f / fmaxf(1.f - px2, 1e-12f);
                }
            }
        }

        // codes: global-warp strided, float4 loads, packed bf16x2 stores
        const int gw  = (int)blockIdx.x * 17 + w;
        const int gws = (int)gridDim.x * 17;
        uint32_t* yh32 = (uint32_t*)g_yhi;
        uint32_t* yl32 = (uint32_t*)g_ylo;
        for (int k = gw; k < K; k += gws) {
            const float4 yv = ((const float4*)(Y + (size_t)k * DD))[lane];
            float s = wsum(fmaf(yv.x, yv.x, fmaf(yv.y, yv.y,
                          fmaf(yv.z, yv.z, yv.w * yv.w))));
            float f0 = yv.x, f1 = yv.y, f2 = yv.z, f3 = yv.w;
            __nv_bfloat16 h0 = __float2bfloat16_rn(f0), h1 = __float2bfloat16_rn(f1);
            __nv_bfloat16 h2 = __float2bfloat16_rn(f2), h3 = __float2bfloat16_rn(f3);
            uint32_t hp0 = (uint32_t)*(uint16_t*)&h0 | ((uint32_t)*(uint16_t*)&h1 << 16);
            uint32_t hp1 = (uint32_t)*(uint16_t*)&h2 | ((uint32_t)*(uint16_t*)&h3 << 16);
            uint32_t lp0 = pack_bf16(f0 - __bfloat162float(h0), f1 - __bfloat162float(h1));
            uint32_t lp1 = pack_bf16(f2 - __bfloat162float(h2), f3 - __bfloat162float(h3));
            size_t base = (size_t)k * 64 + 2 * lane;
            yh32[base] = hp0; yh32[base + 1] = hp1;
            yl32[base] = lp0; yl32[base + 1] = lp1;
            if (lane == 0) {
                float ry = 1.f / fmaxf(1.f - s, 1e-12f);
                g_cc[k] = make_float4(s, ry, fb[k], 0.f);
            }
        }

        // ---- grid barrier (all 148 blocks co-resident: 1 CTA/SM) ----
        __threadfence();
        __syncthreads();
        if (tid == 0) {
            atomicAdd(&g_barA, 1u);
            while (*(volatile unsigned*)&g_barA < gridDim.x) {}
            __threadfence();
        }
        __syncthreads();
    }

    // =================== phase 1: GEMM + fused epilogue =====================
    const int NT = K >> 7;
    const int total = (NROW >> 7) * NT;
    // balanced partition: base tiles per block, first `extra` blocks get +1
    const int base = total / (int)gridDim.x;
    const int extra = total - base * (int)gridDim.x;
    int t = (int)blockIdx.x * base + min((int)blockIdx.x, extra);
    const int tend = t + base + ((int)blockIdx.x < extra ? 1 : 0);

    const float T = __ldg(temp);
    const float nit2 = -1.f / (T * T);
    const float c2 = nit2 * 0.4804530139182014f;   // nit2 * ln(2)^2

#if TC_OK
    if (w == 0) tm_alloc(sb + SM_TMEMPTR, 512);
    __syncthreads();
    uint32_t tbase;
    asm volatile("ld.shared.b32 %0, [%1];" : "=r"(tbase) : "r"(sb + SM_TMEMPTR));

    float* x2a = (float*)(smem + SM_SXR);
    float* rxa = x2a + 128;
    const int sp = w & 3;                          // TMEM subpartition = code group
    const int cq = w >> 2;                         // col quarter = P-row group (0..3)
    const bool kfast = (K == 32000);

    // tile-invariant fill offsets (consumers only; 8 chunks per thread)
    uint32_t foff[8];
    int      fsrc[8];
    bool     fsel[8];
    if (w < 16) {
        #pragma unroll
        for (int k = 0; k < 8; k++) {
            int idx = tid + NCONS * k;
            int s = idx >> 11, f = idx & 2047;
            int r = f >> 4, g = f & 15;
            foff[k] = (uint32_t)s * 32768u + tile_off(r, g);
            fsrc[k] = r * DD + g * 8;
            fsel[k] = (s != 0);
        }
    }

    while (t < tend) {
        const int m  = t / NT;
        const int n0 = t % NT;
        const int L  = min(tend, (m + 1) * NT) - t;

        // ---- segment init: fresh mbarriers + row-const tables ----
        __syncthreads();
        if (tid == 0) {
            #pragma unroll
            for (int s = 0; s < 4; s++) {
                mbar_init(FULLB(s), 1);
                mbar_init(EBB(s), NCONS);
            }
            mbar_init(BFB(0), NCONS);
            mbar_init(BFB(1), NCONS);
        }
        if (tid < 128) {
            x2a[tid] = g_x2[(m << 7) + tid];
            rxa[tid] = g_rx[(m << 7) + tid];
        }
        __syncthreads();

        if (w == 16) {
            // =========== PRODUCER warp: issue MMAs only ===========
            if (lane == 0) {
                mbar_wait(BFB(0), 0);                     // A + Y0 in smem
                fence_async_shared();
                issue_tile(sb + SM_B, sb + SM_A, tbase);
                tm_commit(FULLB(0));
                for (int i = 1; i < L; i++) {
                    if (i >= 4)
                        mbar_wait(EBB(i & 3), (uint32_t)(((i - 4) >> 2) & 1));
                    mbar_wait(BFB(i & 1), (uint32_t)((i >> 1) & 1));
                    fence_async_shared();
                    issue_tile(sb + SM_B + (uint32_t)(i & 1) * 65536u,
                               sb + SM_A,
                               tbase + (uint32_t)(i & 3) * 128u);
                    tm_commit(FULLB(i & 3));
                }
            }
        } else {
            // =========== CONSUMER warps: fill + epilogue ===========
            // prologue fills: A (P tile) + Y0 (+Y1)
            {
                int arow = (m << 7) * DD;
                #pragma unroll
                for (int k = 0; k < 8; k++)
                    cpasync16(sb + SM_A + foff[k],
                              (fsel[k] ? g_plo : g_phi) + arow + fsrc[k]);
                int yrow = (n0 << 7) * DD;
                #pragma unroll
                for (int k = 0; k < 8; k++)
                    cpasync16(sb + SM_B + foff[k],
                              (fsel[k] ? g_ylo : g_yhi) + yrow + fsrc[k]);
                cp_arrive(BFB(0));
                if (L > 1) {
                    int yrow1 = ((n0 + 1) << 7) * DD;
                    #pragma unroll
                    for (int k = 0; k < 8; k++)
                        cpasync16(sb + SM_B + 65536u + foff[k],
                                  (fsel[k] ? g_ylo : g_yhi) + yrow1 + fsrc[k]);
                    cp_arrive(BFB(1));
                }
            }

            for (int j = 0; j < L; j++) {
                const uint32_t slot = (uint32_t)(j & 3);
                // prefetch per-code constants before the wait
                const int code = ((n0 + j) << 7) + (sp << 5) + lane;
                const float4 q = __ldg(&g_cc[code]);    // y2, ry, fb
                mbar_wait(FULLB(slot), (uint32_t)((j >> 2) & 1));
                tm_fence_after();

                // both LDTM chunks back-to-back, then refill while they stream
                const uint32_t dbase = tbase + slot * 128u + (uint32_t)(cq << 5);
                uint32_t r0[16], r1[16];
                ldtm16(r0, dbase);
                ldtm16(r1, dbase + 16u);

                // refill the Y buffer MMA(j) just released with Y(j+2)
                if (j + 2 < L) {
                    uint32_t bb = sb + SM_B + (uint32_t)(j & 1) * 65536u;
                    int yrow = ((n0 + j + 2) << 7) * DD;
                    #pragma unroll
                    for (int k = 0; k < 8; k++)
                        cpasync16(bb + foff[k],
                                  (fsel[k] ? g_ylo : g_yhi) + yrow + fsrc[k]);
                    cp_arrive(BFB(j & 1));
                }

                tm_waitld();
                // D slot is free once data is in registers: release early so
                // the producer can issue MMA(j+4) while we do math/stores.
                mbar_arrive(EBB(slot));

                const uint64_t qx2 = pk2(q.x, q.x);
                const uint64_t qy2 = pk2(q.y, q.y);
                float* obase = out + (size_t)((m << 7) + (cq << 5)) * K + code;
                if (kfast) {
                    epi_block<32000>(r0, x2a + (cq << 5), rxa + (cq << 5), 0,
                                     qx2, qy2, q.z, c2, obase, K);
                    epi_block<32000>(r1, x2a + (cq << 5), rxa + (cq << 5), 8,
                                     qx2, qy2, q.z, c2, obase, K);
                } else {
                    epi_block<0>(r0, x2a + (cq << 5), rxa + (cq << 5), 0,
                                 qx2, qy2, q.z, c2, obase, K);
                    epi_block<0>(r1, x2a + (cq << 5), rxa + (cq << 5), 8,
                                 qx2, qy2, q.z, c2, obase, K);
                }
            }
        }
        t += L;
    }
    __syncthreads();
    if (w == 0) tm_dealloc(tbase, 512);
#else
    // -------- fallback (plain sm_103 cubin; GB300 loads the sm_103a one) ----
    float* Af = (float*)(smem);            // Af[d][m]
    float* Bf = (float*)(smem + 65536);    // Bf[d][n]
    const int tn = tid & 15, tm = (tid >> 4) & 15;
    const bool active = tid < 256;
    int cur_m = -1;
    while (t < tend) {
        const int m = t / NT, n = t % NT;
        __syncthreads();
        if (m != cur_m) {
            for (int idx = tid; idx < 128 * 128; idx += NTHREADS) {
                int r = idx >> 7, d = idx & 127;
                size_t o = (size_t)((m << 7) + r) * DD + d;
                Af[d * 128 + r] = __bfloat162float(g_phi[o]) + __bfloat162float(g_plo[o]);
            }
            cur_m = m;
        }
        for (int idx = tid; idx < 128 * 128; idx += NTHREADS) {
            int r = idx >> 7, d = idx & 127;
            size_t o = (size_t)((n << 7) + r) * DD + d;
            Bf[d * 128 + r] = __bfloat162float(g_yhi[o]) + __bfloat162float(g_ylo[o]);
        }
        __syncthreads();
        if (active) {
            float acc[8][8];
            #pragma unroll
            for (int i = 0; i < 8; i++)
                #pragma unroll
                for (int j = 0; j < 8; j++) acc[i][j] = 0.f;
            for (int d = 0; d < 128; d++) {
                float av[8], bv[8];
                #pragma unroll
                for (int i = 0; i < 8; i++) av[i] = Af[d * 128 + tm * 8 + i];
                #pragma unroll
                for (int j = 0; j < 8; j++) bv[j] = Bf[d * 128 + tn * 8 + j];
                #pragma unroll
                for (int i = 0; i < 8; i++)
                    #pragma unroll
                    for (int j = 0; j < 8; j++) acc[i][j] = fmaf(av[i], bv[j], acc[i][j]);
            }
            #pragma unroll
            for (int i = 0; i < 8; i++) {
                int grow = (m << 7) + tm * 8 + i;
                float x2r = g_x2[grow], rxr = g_rx[grow];
                #pragma unroll
                for (int j = 0; j < 8; j++) {
                    int c = (n << 7) + tn * 8 + j;
                    float4 q = g_cc[c];
                    out[(size_t)grow * K + c] =
                        hd_logit(acc[i][j], x2r, rxr, q.x, q.y, q.z, nit2);
                }
            }
        }
        t++;
    }
#endif

    // ---- exit: last block resets the grid-barrier counters for replay ------
    if (tid == 0) {
        unsigned x = atomicAdd(&g_barB, 1u);
        if (x == gridDim.x - 1) {
            *(volatile unsigned*)&g_barA = 0;
            *(volatile unsigned*)&g_barB = 0;
            __threadfence();
        }
    }
}

// -------------------- launch -------------------------------------------------
extern "C" void kernel_launch(void* const* d_in, const int* in_sizes, int n_in,
                              void* d_out, int out_size) {
    const float* v     = (const float*)d_in[0];
    const float* codes = (const float*)d_in[1];
    const float* W     = (const float*)d_in[2];
    const float* b     = (const float*)d_in[3];
    const float* fb    = (const float*)d_in[4];
    const float* temp  = (const float*)d_in[5];

    const int D = in_sizes[3];            // 128
    const int N = in_sizes[0] / D;        // 2048
    const int K = in_sizes[4];            // 32000

    cudaFuncSetAttribute(hd_fused, cudaFuncAttributeMaxDynamicSharedMemorySize,
                         SM_TOTAL);
    hd_fused<<<148, NTHREADS, SM_TOTAL>>>(v, codes, W, b, fb, temp,
                                          (float*)d_out, N, K);
}

// round 15
// speedup vs baseline: 1.0554x; 1.0554x over previous
#include <cuda_runtime.h>
#include <cuda_bf16.h>
#include <cstdint>

#define DD 128
#define NTHREADS 544            // 16 consumer warps + 1 producer warp
#define NCONS 512

#if defined(__CUDA_ARCH__) && defined(__CUDA_ARCH_FEAT_SM103_ALL)
#define TC_OK 1
#else
#define TC_OK 0
#endif

// -------------------- device scratch (no allocations allowed) ---------------
__device__ float g_x2[4096];
__device__ float g_rx[4096];
__device__ float4 g_cc[32768];            // per-code {y2, 1/(1-y2), fb, 0}
__device__ __nv_bfloat16 g_phi[4096 * DD];
__device__ __nv_bfloat16 g_plo[4096 * DD];
__device__ __nv_bfloat16 g_yhi[32768 * DD];
__device__ __nv_bfloat16 g_ylo[32768 * DD];
__device__ unsigned g_barA;
__device__ unsigned g_barB;

// -------------------- small helpers ----------------------------------------
__device__ __forceinline__ float wsum(float v) {
    #pragma unroll
    for (int o = 16; o > 0; o >>= 1) v += __shfl_xor_sync(0xffffffffu, v, o);
    return v;
}

__device__ __forceinline__ uint32_t s2u(const void* p) {
    uint32_t a;
    asm("{ .reg .u64 t; cvta.to.shared.u64 t, %1; cvt.u32.u64 %0, t; }"
        : "=r"(a) : "l"(p));
    return a;
}

__device__ __forceinline__ void cpasync16(uint32_t dst, const void* src) {
    asm volatile("cp.async.cg.shared.global [%0], [%1], 16;" :: "r"(dst), "l"(src));
}

__device__ __forceinline__ void mbar_init(uint32_t a, uint32_t cnt) {
    asm volatile("mbarrier.init.shared.b64 [%0], %1;" :: "r"(a), "r"(cnt) : "memory");
}
// HW-sleep wait (suspend-time hint -> no issue-slot burn while waiting)
__device__ __forceinline__ void mbar_wait(uint32_t a, uint32_t parity) {
    asm volatile(
        "{\n\t.reg .pred P;\n"
        "W%=:\n\t"
        "mbarrier.try_wait.parity.acquire.cta.shared::cta.b64 P, [%0], %1, 0x989680;\n\t"
        "@!P bra W%=;\n\t}"
        :: "r"(a), "r"(parity) : "memory");
}
__device__ __forceinline__ void mbar_arrive(uint32_t a) {
    asm volatile("mbarrier.arrive.shared.b64 _, [%0];" :: "r"(a) : "memory");
}
__device__ __forceinline__ void cp_arrive(uint32_t a) {
    asm volatile("cp.async.mbarrier.arrive.noinc.shared.b64 [%0];"
                 :: "r"(a) : "memory");
}
__device__ __forceinline__ float sqrt_approx(float x) {
    float r;
    asm("sqrt.approx.f32 %0, %1;" : "=f"(r) : "f"(x));
    return r;
}

// -------------------- packed f32x2 ops (Blackwell) ---------------------------
__device__ __forceinline__ uint64_t pk2(float lo, float hi) {
    uint64_t r;
    asm("mov.b64 %0, {%1, %2};" : "=l"(r) : "f"(lo), "f"(hi));
    return r;
}
__device__ __forceinline__ void unpk2(uint64_t v, float& lo, float& hi) {
    asm("mov.b64 {%0, %1}, %2;" : "=f"(lo), "=f"(hi) : "l"(v));
}
__device__ __forceinline__ uint64_t add2(uint64_t a, uint64_t b) {
    uint64_t r; asm("add.rn.f32x2 %0, %1, %2;" : "=l"(r) : "l"(a), "l"(b)); return r;
}
__device__ __forceinline__ uint64_t mul2(uint64_t a, uint64_t b) {
    uint64_t r; asm("mul.rn.f32x2 %0, %1, %2;" : "=l"(r) : "l"(a), "l"(b)); return r;
}
__device__ __forceinline__ uint64_t fma2v(uint64_t a, uint64_t b, uint64_t c) {
    uint64_t r; asm("fma.rn.f32x2 %0, %1, %2, %3;" : "=l"(r) : "l"(a), "l"(b), "l"(c)); return r;
}

#if TC_OK
__device__ __forceinline__ void tm_alloc(uint32_t smem_res, uint32_t ncols) {
    asm volatile("tcgen05.alloc.cta_group::1.sync.aligned.shared::cta.b32 [%0], %1;"
                 :: "r"(smem_res), "r"(ncols) : "memory");
}
__device__ __forceinline__ void tm_dealloc(uint32_t tmem, uint32_t ncols) {
    asm volatile("tcgen05.dealloc.cta_group::1.sync.aligned.b32 %0, %1;" :: "r"(tmem), "r"(ncols));
}
__device__ __forceinline__ void tm_commit(uint32_t mbar) {
    asm volatile("tcgen05.commit.cta_group::1.mbarrier::arrive::one.shared::cluster.b64 [%0];"
                 :: "r"(mbar) : "memory");
}
__device__ __forceinline__ void tm_fence_after() {
    asm volatile("tcgen05.fence::after_thread_sync;" ::: "memory");
}
__device__ __forceinline__ void fence_async_shared() {
    asm volatile("fence.proxy.async.shared::cta;" ::: "memory");
}
__device__ __forceinline__ void tm_waitld() {
    asm volatile("tcgen05.wait::ld.sync.aligned;" ::: "memory");
}
__device__ __forceinline__ void ldtm16(uint32_t* r, uint32_t a) {
    asm volatile("tcgen05.ld.sync.aligned.32x32b.x16.b32 "
                 "{%0,%1,%2,%3,%4,%5,%6,%7,%8,%9,%10,%11,%12,%13,%14,%15}, [%16];"
                 : "=r"(r[0]), "=r"(r[1]), "=r"(r[2]),  "=r"(r[3]),
                   "=r"(r[4]), "=r"(r[5]), "=r"(r[6]),  "=r"(r[7]),
                   "=r"(r[8]), "=r"(r[9]), "=r"(r[10]), "=r"(r[11]),
                   "=r"(r[12]), "=r"(r[13]), "=r"(r[14]), "=r"(r[15])
                 : "r"(a));
}

// SS bf16 MMA, cg1, fp32 accumulate. M=128, N=128.
#define IDESC_BF16_128x128 ((1u<<4)|(1u<<7)|(1u<<10)|((128u/8u)<<17)|((128u/16u)<<24))

__device__ __forceinline__ void mma_ss(uint32_t d, uint64_t a, uint64_t b,
                                       uint32_t en) {
    asm volatile(
        "{\n\t.reg .pred p;\n\t"
        "setp.ne.u32 p, %5, 0;\n\t"
        "tcgen05.mma.cta_group::1.kind::f16 [%0], %1, %2, %3, {%4, %4, %4, %4}, p;\n\t}"
        :: "r"(d), "l"(a), "l"(b), "r"(IDESC_BF16_128x128), "r"(0u), "r"(en)
        : "memory");
}
#endif  // TC_OK

// 64-bit SMEM descriptor: SW128, version 1 (Blackwell), SBO=64, LBO=1
__device__ __forceinline__ uint64_t mkdesc(uint32_t addr) {
    return ((uint64_t)2 << 61) | ((uint64_t)1 << 46) | ((uint64_t)64 << 32)
         | ((uint64_t)1 << 16) | (uint64_t)((addr >> 4) & 0x3FFFu);
}

// Atom-blocked SW128 offset for a 128-row x 128-col bf16 tile.
__device__ __forceinline__ uint32_t tile_off(int r, int g) {
    uint32_t lin = (uint32_t)((r >> 3) + ((g >> 3) << 4)) * 1024u
                 + (uint32_t)(r & 7) * 128u + (uint32_t)(g & 7) * 16u;
    return lin ^ ((lin >> 3) & 0x70u);
}

// -------------------- smem layout --------------------------------------------
#define SM_TMEMPTR 0
#define SM_MBAR    8                             // 10 mbars x 8B
#define SM_A       1024                          // P: hi 32KB + lo 32KB
#define SM_B       (SM_A + 65536)                // Y: 2 x (hi 32KB + lo 32KB); W^T in prep
#define SM_SXR     (SM_B + 131072)               // x2[128] floats, rx[128] floats
#define SM_TOTAL   (SM_SXR + 1024)

#define FULLB(s) (sb + SM_MBAR + (uint32_t)(s) * 8u)
#define EBB(s)   (sb + SM_MBAR + 32u + (uint32_t)(s) * 8u)
#define BFB(b)   (sb + SM_MBAR + 64u + (uint32_t)(b) * 8u)

#if TC_OK
// A = Y (sa_y), B = P (sb_p): D[code, row]
__device__ __forceinline__ void issue_tile(uint32_t sa_y, uint32_t sb_p, uint32_t d) {
    uint64_t ah = mkdesc(sa_y), al = mkdesc(sa_y + 32768u);
    uint64_t bh = mkdesc(sb_p), bl = mkdesc(sb_p + 32768u);
    #pragma unroll
    for (int kk = 0; kk < 8; kk++) {
        uint32_t off = (uint32_t)(kk >> 2) * 1024u + (uint32_t)(kk & 3) * 2u;
        mma_ss(d, ah + off, bh + off, kk > 0 ? 1u : 0u);
        mma_ss(d, ah + off, bl + off, 1u);
        mma_ss(d, al + off, bh + off, 1u);
    }
}

// packed epilogue for 8 element-pairs (16 rows) from one ldtm16 chunk.
template<int KC>
__device__ __forceinline__ void epi_block(const uint32_t* __restrict__ r,
                                          const float* __restrict__ x2a,
                                          const float* __restrict__ rxa,
                                          int pbase,
                                          uint64_t qx2, uint64_t qy2,
                                          float qz, float c2,
                                          float* __restrict__ obase, int Krt) {
    const uint64_t NEG2  = pk2(-2.f, -2.f);
    const uint64_t ONE2  = pk2(1.f, 1.f);
    const uint64_t MONE2 = pk2(-1.f, -1.f);
    #pragma unroll
    for (int p = 0; p < 8; p++) {
        const int pp = pbase + p;
        float2 x2p = *(const float2*)(x2a + 2 * pp);
        float2 rxp = *(const float2*)(rxa + 2 * pp);
        uint64_t xv2 = pk2(__uint_as_float(r[2 * p]), __uint_as_float(r[2 * p + 1]));
        uint64_t s2  = add2(pk2(x2p.x, x2p.y), qx2);
        uint64_t u2  = fma2v(xv2, NEG2, s2);
        float u0, u1; unpk2(u2, u0, u1);
        u0 = fmaxf(u0, 0.f); u1 = fmaxf(u1, 0.f);
        uint64_t rr2 = mul2(pk2(rxp.x, rxp.y), qy2);
        uint64_t t2  = fma2v(pk2(u0, u1), rr2, ONE2);
        uint64_t a2  = fma2v(t2, t2, MONE2);
        float t0, t1; unpk2(t2, t0, t1);
        float a0, a1; unpk2(a2, a0, a1);
        float w0 = sqrt_approx(a0), w1 = sqrt_approx(a1);
        float l0 = __log2f(t0 + w0), l1 = __log2f(t1 + w1);
        float res0 = fmaf(l0 * l0, c2, qz);
        float res1 = fmaf(l1 * l1, c2, qz);
        if (KC > 0) {
            __stcs(obase + (size_t)(2 * pp) * KC, res0);
            __stcs(obase + (size_t)(2 * pp + 1) * KC, res1);
        } else {
            __stcs(obase + (size_t)(2 * pp) * Krt, res0);
            __stcs(obase + (size_t)(2 * pp + 1) * Krt, res1);
        }
    }
}
#endif

__device__ __forceinline__ float hd_logit(float xv, float x2r, float rxr,
                                          float y2c, float ryc, float fbc,
                                          float nit2) {
    float u = fmaxf(fmaf(-2.f, xv, x2r + y2c), 0.f);
    float t = fmaf(u, rxr * ryc, 1.f);
    float a = fmaf(t, t, -1.f);
    float w = sqrt_approx(a);
    float l = __logf(t + w);
    return fmaf(l * l, nit2, fbc);
}

__device__ __forceinline__ uint32_t pack_bf16(float a, float b) {
    __nv_bfloat16 ha = __float2bfloat16_rn(a), hb = __float2bfloat16_rn(b);
    uint16_t ua = *(uint16_t*)&ha, ub = *(uint16_t*)&hb;
    return (uint32_t)ua | ((uint32_t)ub << 16);
}

// ======================= the single fused kernel =============================
__global__ void __launch_bounds__(NTHREADS, 1)
hd_fused(const float* __restrict__ V, const float* __restrict__ Y,
         const float* __restrict__ W, const float* __restrict__ bvec,
         const float* __restrict__ fb, const float* __restrict__ temp,
         float* __restrict__ out, int NROW, int K) {
    extern __shared__ char smem[];
    uint32_t sb = s2u(smem);
    int tid = threadIdx.x, w = tid >> 5, lane = tid & 31;

    // =================== phase 0: prep (rows + codes) =======================
    {
        const int nrowblk = (NROW + 15) >> 4;        // 16 rows per block
        if ((int)blockIdx.x < nrowblk) {
            float* sWt = (float*)(smem + SM_B);
            for (int idx = tid; idx < DD * DD; idx += NTHREADS) {
                int d = idx >> 7, e = idx & 127;
                sWt[e * 132 + d] = W[idx];
            }
            __syncthreads();
            int row = ((int)blockIdx.x << 4) + w;
            if (w < 16 && row < NROW) {
                const float* v = V + (size_t)row * DD;
                float vq[4];
                #pragma unroll
                for (int q = 0; q < 4; q++) vq[q] = v[lane + 32 * q];
                float n2 = wsum(vq[0]*vq[0] + vq[1]*vq[1] + vq[2]*vq[2] + vq[3]*vq[3]);
                float n  = sqrtf(fmaxf(n2, 1e-30f));
                float xn = tanhf(n);
                float s0 = xn / n;
                float p0[4];
                #pragma unroll
                for (int q = 0; q < 4; q++) p0[q] = s0 * vq[q];

                float mq[4] = {0.f, 0.f, 0.f, 0.f};
                #pragma unroll
                for (int e = 0; e < DD; e++) {
                    float pe = __shfl_sync(0xffffffffu, p0[e >> 5], e & 31);
                    #pragma unroll
                    for (int q = 0; q < 4; q++)
                        mq[q] = fmaf(pe, sWt[e * 132 + 32 * q + lane], mq[q]);
                }
                float mxn2 = wsum(mq[0]*mq[0] + mq[1]*mq[1] + mq[2]*mq[2] + mq[3]*mq[3]);
                float mxn  = sqrtf(fmaxf(mxn2, 1e-30f));
                float xc   = fminf(xn, 1.f - 1e-5f);
                float ath  = 0.5f * __logf((1.f + xc) / (1.f - xc));
                float g    = tanhf(mxn / fmaxf(xn, 1e-15f) * ath) / mxn;
                float rq[4];
                #pragma unroll
                for (int q = 0; q < 4; q++) rq[q] = g * mq[q];

                float bq[4];
                #pragma unroll
                for (int q = 0; q < 4; q++) bq[q] = bvec[lane + 32 * q];
                float bn2 = wsum(bq[0]*bq[0] + bq[1]*bq[1] + bq[2]*bq[2] + bq[3]*bq[3]);
                float bn  = sqrtf(fmaxf(bn2, 1e-30f));
                float tb  = tanhf(bn);
                float sb2 = tb / bn;
                float ebq[4];
                #pragma unroll
                for (int q = 0; q < 4; q++) ebq[q] = sb2 * bq[q];
                float y2 = tb * tb;

                float x2 = wsum(rq[0]*rq[0] + rq[1]*rq[1] + rq[2]*rq[2] + rq[3]*rq[3]);
                float xy = wsum(rq[0]*ebq[0] + rq[1]*ebq[1] + rq[2]*ebq[2] + rq[3]*ebq[3]);
                float ca  = 1.f + 2.f * xy + y2;
                float cb  = 1.f - x2;
                float den = fmaxf(1.f + 2.f * xy + x2 * y2, 1e-15f);
                float inv = 1.f / den;
                float pq[4], ps = 0.f;
                #pragma unroll
                for (int q = 0; q < 4; q++) {
                    pq[q] = (ca * rq[q] + cb * ebq[q]) * inv;
                    ps = fmaf(pq[q], pq[q], ps);
                }
                float px2 = wsum(ps);
                #pragma unroll
                for (int q = 0; q < 4; q++) {
                    int d = lane + 32 * q;
                    __nv_bfloat16 hi = __float2bfloat16_rn(pq[q]);
                    __nv_bfloat16 lo = __float2bfloat16_rn(pq[q] - __bfloat162float(hi));
                    g_phi[(size_t)row * DD + d] = hi;
                    g_plo[(size_t)row * DD + d] = lo;
                }
                if (lane == 0) {
                    g_x2[row] = px2;
                    g_rx[row] = 2.f / fmaxf(1.f - px2, 1e-12f);
                }
            }
        }

        // codes: global-warp strided, float4 loads, packed bf16x2 stores
        const int gw  = (int)blockIdx.x * 17 + w;
        const int gws = (int)gridDim.x * 17;
        uint32_t* yh32 = (uint32_t*)g_yhi;
        uint32_t* yl32 = (uint32_t*)g_ylo;
        for (int k = gw; k < K; k += gws) {
            const float4 yv = ((const float4*)(Y + (size_t)k * DD))[lane];
            float s = wsum(fmaf(yv.x, yv.x, fmaf(yv.y, yv.y,
                          fmaf(yv.z, yv.z, yv.w * yv.w))));
            float f0 = yv.x, f1 = yv.y, f2 = yv.z, f3 = yv.w;
            __nv_bfloat16 h0 = __float2bfloat16_rn(f0), h1 = __float2bfloat16_rn(f1);
            __nv_bfloat16 h2 = __float2bfloat16_rn(f2), h3 = __float2bfloat16_rn(f3);
            uint32_t hp0 = (uint32_t)*(uint16_t*)&h0 | ((uint32_t)*(uint16_t*)&h1 << 16);
            uint32_t hp1 = (uint32_t)*(uint16_t*)&h2 | ((uint32_t)*(uint16_t*)&h3 << 16);
            uint32_t lp0 = pack_bf16(f0 - __bfloat162float(h0), f1 - __bfloat162float(h1));
            uint32_t lp1 = pack_bf16(f2 - __bfloat162float(h2), f3 - __bfloat162float(h3));
            size_t base = (size_t)k * 64 + 2 * lane;
            yh32[base] = hp0; yh32[base + 1] = hp1;
            yl32[base] = lp0; yl32[base + 1] = lp1;
            if (lane == 0) {
                float ry = 1.f / fmaxf(1.f - s, 1e-12f);
                g_cc[k] = make_float4(s, ry, fb[k], 0.f);
            }
        }

        // ---- grid barrier (all 148 blocks co-resident: 1 CTA/SM) ----
        __threadfence();
        __syncthreads();
        if (tid == 0) {
            atomicAdd(&g_barA, 1u);
            while (*(volatile unsigned*)&g_barA < gridDim.x) {}
            __threadfence();
        }
        __syncthreads();
    }

    // =================== phase 1: GEMM + fused epilogue =====================
    const int NT = K >> 7;
    const int total = (NROW >> 7) * NT;
    // balanced partition: base tiles per block, first `extra` blocks get +1
    const int base = total / (int)gridDim.x;
    const int extra = total - base * (int)gridDim.x;
    int t = (int)blockIdx.x * base + min((int)blockIdx.x, extra);
    const int tend = t + base + ((int)blockIdx.x < extra ? 1 : 0);

    const float T = __ldg(temp);
    const float nit2 = -1.f / (T * T);
    const float c2 = nit2 * 0.4804530139182014f;   // nit2 * ln(2)^2

#if TC_OK
    if (w == 0) tm_alloc(sb + SM_TMEMPTR, 512);
    __syncthreads();
    uint32_t tbase;
    asm volatile("ld.shared.b32 %0, [%1];" : "=r"(tbase) : "r"(sb + SM_TMEMPTR));

    float* x2a = (float*)(smem + SM_SXR);
    float* rxa = x2a + 128;
    const int sp = w & 3;                          // TMEM subpartition = code group
    const int cq = w >> 2;                         // col quarter = P-row group (0..3)
    const bool kfast = (K == 32000);

    // tile-invariant fill offsets (consumers only; 8 chunks per thread)
    uint32_t foff[8];
    int      fsrc[8];
    bool     fsel[8];
    if (w < 16) {
        #pragma unroll
        for (int k = 0; k < 8; k++) {
            int idx = tid + NCONS * k;
            int s = idx >> 11, f = idx & 2047;
            int r = f >> 4, g = f & 15;
            foff[k] = (uint32_t)s * 32768u + tile_off(r, g);
            fsrc[k] = r * DD + g * 8;
            fsel[k] = (s != 0);
        }
    }

    while (t < tend) {
        const int m  = t / NT;
        const int n0 = t % NT;
        const int L  = min(tend, (m + 1) * NT) - t;

        // ---- segment init: fresh mbarriers + row-const tables ----
        __syncthreads();
        if (tid == 0) {
            #pragma unroll
            for (int s = 0; s < 4; s++) {
                mbar_init(FULLB(s), 1);
                mbar_init(EBB(s), NCONS);
            }
            mbar_init(BFB(0), NCONS);
            mbar_init(BFB(1), NCONS);
        }
        if (tid < 128) {
            x2a[tid] = g_x2[(m << 7) + tid];
            rxa[tid] = g_rx[(m << 7) + tid];
        }
        __syncthreads();

        if (w == 16) {
            // =========== PRODUCER warp: issue MMAs only ===========
            if (lane == 0) {
                mbar_wait(BFB(0), 0);                     // A + Y0 in smem
                fence_async_shared();
                issue_tile(sb + SM_B, sb + SM_A, tbase);
                tm_commit(FULLB(0));
                for (int i = 1; i < L; i++) {
                    if (i >= 4)
                        mbar_wait(EBB(i & 3), (uint32_t)(((i - 4) >> 2) & 1));
                    mbar_wait(BFB(i & 1), (uint32_t)((i >> 1) & 1));
                    fence_async_shared();
                    issue_tile(sb + SM_B + (uint32_t)(i & 1) * 65536u,
                               sb + SM_A,
                               tbase + (uint32_t)(i & 3) * 128u);
                    tm_commit(FULLB(i & 3));
                }
            }
        } else {
            // =========== CONSUMER warps: fill + epilogue ===========
            // prologue fills: A (P tile) + Y0 (+Y1)
            {
                int arow = (m << 7) * DD;
                #pragma unroll
                for (int k = 0; k < 8; k++)
                    cpasync16(sb + SM_A + foff[k],
                              (fsel[k] ? g_plo : g_phi) + arow + fsrc[k]);
                int yrow = (n0 << 7) * DD;
                #pragma unroll
                for (int k = 0; k < 8; k++)
                    cpasync16(sb + SM_B + foff[k],
                              (fsel[k] ? g_ylo : g_yhi) + yrow + fsrc[k]);
                cp_arrive(BFB(0));
                if (L > 1) {
                    int yrow1 = ((n0 + 1) << 7) * DD;
                    #pragma unroll
                    for (int k = 0; k < 8; k++)
                        cpasync16(sb + SM_B + 65536u + foff[k],
                                  (fsel[k] ? g_ylo : g_yhi) + yrow1 + fsrc[k]);
                    cp_arrive(BFB(1));
                }
            }

            for (int j = 0; j < L; j++) {
                const uint32_t slot = (uint32_t)(j & 3);
                // prefetch per-code constants before the wait
                const int code = ((n0 + j) << 7) + (sp << 5) + lane;
                const float4 q = __ldg(&g_cc[code]);    // y2, ry, fb
                mbar_wait(FULLB(slot), (uint32_t)((j >> 2) & 1));
                tm_fence_after();

                // first LDTM chunk, then kick refill while it streams
                const uint32_t dbase = tbase + slot * 128u + (uint32_t)(cq << 5);
                uint32_t r0[16], r1[16];
                ldtm16(r0, dbase);

                // refill the Y buffer MMA(j) just released with Y(j+2)
                if (j + 2 < L) {
                    uint32_t bb = sb + SM_B + (uint32_t)(j & 1) * 65536u;
                    int yrow = ((n0 + j + 2) << 7) * DD;
                    #pragma unroll
                    for (int k = 0; k < 8; k++)
                        cpasync16(bb + foff[k],
                                  (fsel[k] ? g_ylo : g_yhi) + yrow + fsrc[k]);
                    cp_arrive(BFB(j & 1));
                }

                tm_waitld();
                ldtm16(r1, dbase + 16u);                 // streams during math

                const uint64_t qx2 = pk2(q.x, q.x);
                const uint64_t qy2 = pk2(q.y, q.y);
                float* obase = out + (size_t)((m << 7) + (cq << 5)) * K + code;
                if (kfast) {
                    epi_block<32000>(r0, x2a + (cq << 5), rxa + (cq << 5), 0,
                                     qx2, qy2, q.z, c2, obase, K);
                    tm_waitld();
                    epi_block<32000>(r1, x2a + (cq << 5), rxa + (cq << 5), 8,
                                     qx2, qy2, q.z, c2, obase, K);
                } else {
                    epi_block<0>(r0, x2a + (cq << 5), rxa + (cq << 5), 0,
                                 qx2, qy2, q.z, c2, obase, K);
                    tm_waitld();
                    epi_block<0>(r1, x2a + (cq << 5), rxa + (cq << 5), 8,
                                 qx2, qy2, q.z, c2, obase, K);
                }
                mbar_arrive(EBB(slot));
            }
        }
        t += L;
    }
    __syncthreads();
    if (w == 0) tm_dealloc(tbase, 512);
#else
    // -------- fallback (plain sm_103 cubin; GB300 loads the sm_103a one) ----
    float* Af = (float*)(smem);            // Af[d][m]
    float* Bf = (float*)(smem + 65536);    // Bf[d][n]
    const int tn = tid & 15, tm = (tid >> 4) & 15;
    const bool active = tid < 256;
    int cur_m = -1;
    while (t < tend) {
        const int m = t / NT, n = t % NT;
        __syncthreads();
        if (m != cur_m) {
            for (int idx = tid; idx < 128 * 128; idx += NTHREADS) {
                int r = idx >> 7, d = idx & 127;
                size_t o = (size_t)((m << 7) + r) * DD + d;
                Af[d * 128 + r] = __bfloat162float(g_phi[o]) + __bfloat162float(g_plo[o]);
            }
            cur_m = m;
        }
        for (int idx = tid; idx < 128 * 128; idx += NTHREADS) {
            int r = idx >> 7, d = idx & 127;
            size_t o = (size_t)((n << 7) + r) * DD + d;
            Bf[d * 128 + r] = __bfloat162float(g_yhi[o]) + __bfloat162float(g_ylo[o]);
        }
        __syncthreads();
        if (active) {
            float acc[8][8];
            #pragma unroll
            for (int i = 0; i < 8; i++)
                #pragma unroll
                for (int j = 0; j < 8; j++) acc[i][j] = 0.f;
            for (int d = 0; d < 128; d++) {
                float av[8], bv[8];
                #pragma unroll
                for (int i = 0; i < 8; i++) av[i] = Af[d * 128 + tm * 8 + i];
                #pragma unroll
                for (int j = 0; j < 8; j++) bv[j] = Bf[d * 128 + tn * 8 + j];
                #pragma unroll
                for (int i = 0; i < 8; i++)
                    #pragma unroll
                    for (int j = 0; j < 8; j++) acc[i][j] = fmaf(av[i], bv[j], acc[i][j]);
            }
            #pragma unroll
            for (int i = 0; i < 8; i++) {
                int grow = (m << 7) + tm * 8 + i;
                float x2r = g_x2[grow], rxr = g_rx[grow];
                #pragma unroll
                for (int j = 0; j < 8; j++) {
                    int c = (n << 7) + tn * 8 + j;
                    float4 q = g_cc[c];
                    out[(size_t)grow * K + c] =
                        hd_logit(acc[i][j], x2r, rxr, q.x, q.y, q.z, nit2);
                }
            }
        }
        t++;
    }
#endif

    // ---- exit: last block resets the grid-barrier counters for replay ------
    if (tid == 0) {
        unsigned x = atomicAdd(&g_barB, 1u);
        if (x == gridDim.x - 1) {
            *(volatile unsigned*)&g_barA = 0;
            *(volatile unsigned*)&g_barB = 0;
            __threadfence();
        }
    }
}

// -------------------- launch -------------------------------------------------
extern "C" void kernel_launch(void* const* d_in, const int* in_sizes, int n_in,
                              void* d_out, int out_size) {
    const float* v     = (const float*)d_in[0];
    const float* codes = (const float*)d_in[1];
    const float* W     = (const float*)d_in[2];
    const float* b     = (const float*)d_in[3];
    const float* fb    = (const float*)d_in[4];
    const float* temp  = (const float*)d_in[5];

    const int D = in_sizes[3];            // 128
    const int N = in_sizes[0] / D;        // 2048
    const int K = in_sizes[4];            // 32000

    cudaFuncSetAttribute(hd_fused, cudaFuncAttributeMaxDynamicSharedMemorySize,
                         SM_TOTAL);
    hd_fused<<<148, NTHREADS, SM_TOTAL>>>(v, codes, W, b, fb, temp,
                                          (float*)d_out, N, K);
}

// round 16
// speedup vs baseline: 1.1205x; 1.0617x over previous
#include <cuda_runtime.h>
#include <cuda_bf16.h>
#include <cstdint>

#define DD 128
#define NTHREADS 544            // 16 consumer warps + 1 producer warp
#define NCONS 512
#define NGRP 256                // threads per consumer group

#if defined(__CUDA_ARCH__) && defined(__CUDA_ARCH_FEAT_SM103_ALL)
#define TC_OK 1
#else
#define TC_OK 0
#endif

// -------------------- device scratch (no allocations allowed) ---------------
__device__ float g_x2[4096];
__device__ float g_rx[4096];
__device__ float4 g_cc[32768];            // per-code {y2, 1/(1-y2), fb, 0}
__device__ __nv_bfloat16 g_phi[4096 * DD];
__device__ __nv_bfloat16 g_plo[4096 * DD];
__device__ __nv_bfloat16 g_yhi[32768 * DD];
__device__ __nv_bfloat16 g_ylo[32768 * DD];
__device__ unsigned g_barA;
__device__ unsigned g_barB;

// -------------------- small helpers ----------------------------------------
__device__ __forceinline__ float wsum(float v) {
    #pragma unroll
    for (int o = 16; o > 0; o >>= 1) v += __shfl_xor_sync(0xffffffffu, v, o);
    return v;
}

__device__ __forceinline__ uint32_t s2u(const void* p) {
    uint32_t a;
    asm("{ .reg .u64 t; cvta.to.shared.u64 t, %1; cvt.u32.u64 %0, t; }"
        : "=r"(a) : "l"(p));
    return a;
}

__device__ __forceinline__ void cpasync16(uint32_t dst, const void* src) {
    asm volatile("cp.async.cg.shared.global [%0], [%1], 16;" :: "r"(dst), "l"(src));
}

__device__ __forceinline__ void mbar_init(uint32_t a, uint32_t cnt) {
    asm volatile("mbarrier.init.shared.b64 [%0], %1;" :: "r"(a), "r"(cnt) : "memory");
}
// HW-sleep wait (suspend-time hint -> no issue-slot burn while waiting)
__device__ __forceinline__ void mbar_wait(uint32_t a, uint32_t parity) {
    asm volatile(
        "{\n\t.reg .pred P;\n"
        "W%=:\n\t"
        "mbarrier.try_wait.parity.acquire.cta.shared::cta.b64 P, [%0], %1, 0x989680;\n\t"
        "@!P bra W%=;\n\t}"
        :: "r"(a), "r"(parity) : "memory");
}
__device__ __forceinline__ void mbar_arrive(uint32_t a) {
    asm volatile("mbarrier.arrive.shared.b64 _, [%0];" :: "r"(a) : "memory");
}
__device__ __forceinline__ void cp_arrive(uint32_t a) {
    asm volatile("cp.async.mbarrier.arrive.noinc.shared.b64 [%0];"
                 :: "r"(a) : "memory");
}
__device__ __forceinline__ float sqrt_approx(float x) {
    float r;
    asm("sqrt.approx.f32 %0, %1;" : "=f"(r) : "f"(x));
    return r;
}

// -------------------- packed f32x2 ops (Blackwell) ---------------------------
__device__ __forceinline__ uint64_t pk2(float lo, float hi) {
    uint64_t r;
    asm("mov.b64 %0, {%1, %2};" : "=l"(r) : "f"(lo), "f"(hi));
    return r;
}
__device__ __forceinline__ void unpk2(uint64_t v, float& lo, float& hi) {
    asm("mov.b64 {%0, %1}, %2;" : "=f"(lo), "=f"(hi) : "l"(v));
}
__device__ __forceinline__ uint64_t add2(uint64_t a, uint64_t b) {
    uint64_t r; asm("add.rn.f32x2 %0, %1, %2;" : "=l"(r) : "l"(a), "l"(b)); return r;
}
__device__ __forceinline__ uint64_t mul2(uint64_t a, uint64_t b) {
    uint64_t r; asm("mul.rn.f32x2 %0, %1, %2;" : "=l"(r) : "l"(a), "l"(b)); return r;
}
__device__ __forceinline__ uint64_t fma2v(uint64_t a, uint64_t b, uint64_t c) {
    uint64_t r; asm("fma.rn.f32x2 %0, %1, %2, %3;" : "=l"(r) : "l"(a), "l"(b), "l"(c)); return r;
}

#if TC_OK
__device__ __forceinline__ void tm_alloc(uint32_t smem_res, uint32_t ncols) {
    asm volatile("tcgen05.alloc.cta_group::1.sync.aligned.shared::cta.b32 [%0], %1;"
                 :: "r"(smem_res), "r"(ncols) : "memory");
}
__device__ __forceinline__ void tm_dealloc(uint32_t tmem, uint32_t ncols) {
    asm volatile("tcgen05.dealloc.cta_group::1.sync.aligned.b32 %0, %1;" :: "r"(tmem), "r"(ncols));
}
__device__ __forceinline__ void tm_commit(uint32_t mbar) {
    asm volatile("tcgen05.commit.cta_group::1.mbarrier::arrive::one.shared::cluster.b64 [%0];"
                 :: "r"(mbar) : "memory");
}
__device__ __forceinline__ void tm_fence_after() {
    asm volatile("tcgen05.fence::after_thread_sync;" ::: "memory");
}
__device__ __forceinline__ void fence_async_shared() {
    asm volatile("fence.proxy.async.shared::cta;" ::: "memory");
}
__device__ __forceinline__ void tm_waitld() {
    asm volatile("tcgen05.wait::ld.sync.aligned;" ::: "memory");
}
__device__ __forceinline__ void ldtm16(uint32_t* r, uint32_t a) {
    asm volatile("tcgen05.ld.sync.aligned.32x32b.x16.b32 "
                 "{%0,%1,%2,%3,%4,%5,%6,%7,%8,%9,%10,%11,%12,%13,%14,%15}, [%16];"
                 : "=r"(r[0]), "=r"(r[1]), "=r"(r[2]),  "=r"(r[3]),
                   "=r"(r[4]), "=r"(r[5]), "=r"(r[6]),  "=r"(r[7]),
                   "=r"(r[8]), "=r"(r[9]), "=r"(r[10]), "=r"(r[11]),
                   "=r"(r[12]), "=r"(r[13]), "=r"(r[14]), "=r"(r[15])
                 : "r"(a));
}

// SS bf16 MMA, cg1, fp32 accumulate. M=128, N=128.
#define IDESC_BF16_128x128 ((1u<<4)|(1u<<7)|(1u<<10)|((128u/8u)<<17)|((128u/16u)<<24))

__device__ __forceinline__ void mma_ss(uint32_t d, uint64_t a, uint64_t b,
                                       uint32_t en) {
    asm volatile(
        "{\n\t.reg .pred p;\n\t"
        "setp.ne.u32 p, %5, 0;\n\t"
        "tcgen05.mma.cta_group::1.kind::f16 [%0], %1, %2, %3, {%4, %4, %4, %4}, p;\n\t}"
        :: "r"(d), "l"(a), "l"(b), "r"(IDESC_BF16_128x128), "r"(0u), "r"(en)
        : "memory");
}
#endif  // TC_OK

// 64-bit SMEM descriptor: SW128, version 1 (Blackwell), SBO=64, LBO=1
__device__ __forceinline__ uint64_t mkdesc(uint32_t addr) {
    return ((uint64_t)2 << 61) | ((uint64_t)1 << 46) | ((uint64_t)64 << 32)
         | ((uint64_t)1 << 16) | (uint64_t)((addr >> 4) & 0x3FFFu);
}

// Atom-blocked SW128 offset for a 128-row x 128-col bf16 tile.
__device__ __forceinline__ uint32_t tile_off(int r, int g) {
    uint32_t lin = (uint32_t)((r >> 3) + ((g >> 3) << 4)) * 1024u
                 + (uint32_t)(r & 7) * 128u + (uint32_t)(g & 7) * 16u;
    return lin ^ ((lin >> 3) & 0x70u);
}

// -------------------- smem layout --------------------------------------------
#define SM_TMEMPTR 0
#define SM_MBAR    8                             // 10 mbars x 8B
#define SM_A       1024                          // P: hi 32KB + lo 32KB
#define SM_B       (SM_A + 65536)                // Y: 2 x (hi 32KB + lo 32KB); W^T in prep
#define SM_SXR     (SM_B + 131072)               // x2[128] floats, rx[128] floats
#define SM_TOTAL   (SM_SXR + 1024)

#define FULLB(s) (sb + SM_MBAR + (uint32_t)(s) * 8u)
#define EBB(s)   (sb + SM_MBAR + 32u + (uint32_t)(s) * 8u)
#define BFB(b)   (sb + SM_MBAR + 64u + (uint32_t)(b) * 8u)

#if TC_OK
// A = Y (sa_y), B = P (sb_p): D[code, row]
__device__ __forceinline__ void issue_tile(uint32_t sa_y, uint32_t sb_p, uint32_t d) {
    uint64_t ah = mkdesc(sa_y), al = mkdesc(sa_y + 32768u);
    uint64_t bh = mkdesc(sb_p), bl = mkdesc(sb_p + 32768u);
    #pragma unroll
    for (int kk = 0; kk < 8; kk++) {
        uint32_t off = (uint32_t)(kk >> 2) * 1024u + (uint32_t)(kk & 3) * 2u;
        mma_ss(d, ah + off, bh + off, kk > 0 ? 1u : 0u);
        mma_ss(d, ah + off, bl + off, 1u);
        mma_ss(d, al + off, bh + off, 1u);
    }
}

// group fill: one full hi+lo tile by 256 threads; foff = 8 hoisted offsets
__device__ __forceinline__ void fill_tile_grp(uint32_t dst,
                                              const __nv_bfloat16* __restrict__ hi,
                                              const __nv_bfloat16* __restrict__ lo,
                                              int rowelem, int ltid,
                                              const uint32_t* foff) {
    #pragma unroll
    for (int k = 0; k < 8; k++) {
        int src = rowelem + 8 * ltid + 2048 * k;
        cpasync16(dst + foff[k], hi + src);
        cpasync16(dst + foff[k] + 32768u, lo + src);
    }
}

// packed epilogue for 8 element-pairs (16 rows) from one ldtm16 chunk.
template<int KC>
__device__ __forceinline__ void epi_block(const uint32_t* __restrict__ r,
                                          const float* __restrict__ x2a,
                                          const float* __restrict__ rxa,
                                          int pbase,
                                          uint64_t qx2, uint64_t qy2,
                                          float qz, float c2,
                                          float* __restrict__ obase, int Krt) {
    const uint64_t NEG2  = pk2(-2.f, -2.f);
    const uint64_t ONE2  = pk2(1.f, 1.f);
    const uint64_t MONE2 = pk2(-1.f, -1.f);
    #pragma unroll
    for (int p = 0; p < 8; p++) {
        const int pp = pbase + p;
        float2 x2p = *(const float2*)(x2a + 2 * pp);
        float2 rxp = *(const float2*)(rxa + 2 * pp);
        uint64_t xv2 = pk2(__uint_as_float(r[2 * p]), __uint_as_float(r[2 * p + 1]));
        uint64_t s2  = add2(pk2(x2p.x, x2p.y), qx2);
        uint64_t u2  = fma2v(xv2, NEG2, s2);
        float u0, u1; unpk2(u2, u0, u1);
        u0 = fmaxf(u0, 0.f); u1 = fmaxf(u1, 0.f);
        uint64_t rr2 = mul2(pk2(rxp.x, rxp.y), qy2);
        uint64_t t2  = fma2v(pk2(u0, u1), rr2, ONE2);
        uint64_t a2  = fma2v(t2, t2, MONE2);
        float t0, t1; unpk2(t2, t0, t1);
        float a0, a1; unpk2(a2, a0, a1);
        float w0 = sqrt_approx(a0), w1 = sqrt_approx(a1);
        float l0 = __log2f(t0 + w0), l1 = __log2f(t1 + w1);
        float res0 = fmaf(l0 * l0, c2, qz);
        float res1 = fmaf(l1 * l1, c2, qz);
        if (KC > 0) {
            __stcs(obase + (size_t)(2 * pp) * KC, res0);
            __stcs(obase + (size_t)(2 * pp + 1) * KC, res1);
        } else {
            __stcs(obase + (size_t)(2 * pp) * Krt, res0);
            __stcs(obase + (size_t)(2 * pp + 1) * Krt, res1);
        }
    }
}
#endif

__device__ __forceinline__ float hd_logit(float xv, float x2r, float rxr,
                                          float y2c, float ryc, float fbc,
                                          float nit2) {
    float u = fmaxf(fmaf(-2.f, xv, x2r + y2c), 0.f);
    float t = fmaf(u, rxr * ryc, 1.f);
    float a = fmaf(t, t, -1.f);
    float w = sqrt_approx(a);
    float l = __logf(t + w);
    return fmaf(l * l, nit2, fbc);
}

__device__ __forceinline__ uint32_t pack_bf16(float a, float b) {
    __nv_bfloat16 ha = __float2bfloat16_rn(a), hb = __float2bfloat16_rn(b);
    uint16_t ua = *(uint16_t*)&ha, ub = *(uint16_t*)&hb;
    return (uint32_t)ua | ((uint32_t)ub << 16);
}

// ======================= the single fused kernel =============================
__global__ void __launch_bounds__(NTHREADS, 1)
hd_fused(const float* __restrict__ V, const float* __restrict__ Y,
         const float* __restrict__ W, const float* __restrict__ bvec,
         const float* __restrict__ fb, const float* __restrict__ temp,
         float* __restrict__ out, int NROW, int K) {
    extern __shared__ char smem[];
    uint32_t sb = s2u(smem);
    int tid = threadIdx.x, w = tid >> 5, lane = tid & 31;

    // =================== phase 0: prep (rows + codes) =======================
    {
        const int nrowblk = (NROW + 15) >> 4;        // 16 rows per block
        if ((int)blockIdx.x < nrowblk) {
            float* sWt = (float*)(smem + SM_B);
            for (int idx = tid; idx < DD * DD; idx += NTHREADS) {
                int d = idx >> 7, e = idx & 127;
                sWt[e * 132 + d] = W[idx];
            }
            __syncthreads();
            int row = ((int)blockIdx.x << 4) + w;
            if (w < 16 && row < NROW) {
                const float* v = V + (size_t)row * DD;
                float vq[4];
                #pragma unroll
                for (int q = 0; q < 4; q++) vq[q] = v[lane + 32 * q];
                float n2 = wsum(vq[0]*vq[0] + vq[1]*vq[1] + vq[2]*vq[2] + vq[3]*vq[3]);
                float n  = sqrtf(fmaxf(n2, 1e-30f));
                float xn = tanhf(n);
                float s0 = xn / n;
                float p0[4];
                #pragma unroll
                for (int q = 0; q < 4; q++) p0[q] = s0 * vq[q];

                float mq[4] = {0.f, 0.f, 0.f, 0.f};
                #pragma unroll
                for (int e = 0; e < DD; e++) {
                    float pe = __shfl_sync(0xffffffffu, p0[e >> 5], e & 31);
                    #pragma unroll
                    for (int q = 0; q < 4; q++)
                        mq[q] = fmaf(pe, sWt[e * 132 + 32 * q + lane], mq[q]);
                }
                float mxn2 = wsum(mq[0]*mq[0] + mq[1]*mq[1] + mq[2]*mq[2] + mq[3]*mq[3]);
                float mxn  = sqrtf(fmaxf(mxn2, 1e-30f));
                float xc   = fminf(xn, 1.f - 1e-5f);
                float ath  = 0.5f * __logf((1.f + xc) / (1.f - xc));
                float g    = tanhf(mxn / fmaxf(xn, 1e-15f) * ath) / mxn;
                float rq[4];
                #pragma unroll
                for (int q = 0; q < 4; q++) rq[q] = g * mq[q];

                float bq[4];
                #pragma unroll
                for (int q = 0; q < 4; q++) bq[q] = bvec[lane + 32 * q];
                float bn2 = wsum(bq[0]*bq[0] + bq[1]*bq[1] + bq[2]*bq[2] + bq[3]*bq[3]);
                float bn  = sqrtf(fmaxf(bn2, 1e-30f));
                float tb  = tanhf(bn);
                float sb2 = tb / bn;
                float ebq[4];
                #pragma unroll
                for (int q = 0; q < 4; q++) ebq[q] = sb2 * bq[q];
                float y2 = tb * tb;

                float x2 = wsum(rq[0]*rq[0] + rq[1]*rq[1] + rq[2]*rq[2] + rq[3]*rq[3]);
                float xy = wsum(rq[0]*ebq[0] + rq[1]*ebq[1] + rq[2]*ebq[2] + rq[3]*ebq[3]);
                float ca  = 1.f + 2.f * xy + y2;
                float cb  = 1.f - x2;
                float den = fmaxf(1.f + 2.f * xy + x2 * y2, 1e-15f);
                float inv = 1.f / den;
                float pq[4], ps = 0.f;
                #pragma unroll
                for (int q = 0; q < 4; q++) {
                    pq[q] = (ca * rq[q] + cb * ebq[q]) * inv;
                    ps = fmaf(pq[q], pq[q], ps);
                }
                float px2 = wsum(ps);
                #pragma unroll
                for (int q = 0; q < 4; q++) {
                    int d = lane + 32 * q;
                    __nv_bfloat16 hi = __float2bfloat16_rn(pq[q]);
                    __nv_bfloat16 lo = __float2bfloat16_rn(pq[q] - __bfloat162float(hi));
                    g_phi[(size_t)row * DD + d] = hi;
                    g_plo[(size_t)row * DD + d] = lo;
                }
                if (lane == 0) {
                    g_x2[row] = px2;
                    g_rx[row] = 2.f / fmaxf(1.f - px2, 1e-12f);
                }
            }
        }

        // codes: global-warp strided, float4 loads, packed bf16x2 stores
        const int gw  = (int)blockIdx.x * 17 + w;
        const int gws = (int)gridDim.x * 17;
        uint32_t* yh32 = (uint32_t*)g_yhi;
        uint32_t* yl32 = (uint32_t*)g_ylo;
        for (int k = gw; k < K; k += gws) {
            const float4 yv = ((const float4*)(Y + (size_t)k * DD))[lane];
            float s = wsum(fmaf(yv.x, yv.x, fmaf(yv.y, yv.y,
                          fmaf(yv.z, yv.z, yv.w * yv.w))));
            float f0 = yv.x, f1 = yv.y, f2 = yv.z, f3 = yv.w;
            __nv_bfloat16 h0 = __float2bfloat16_rn(f0), h1 = __float2bfloat16_rn(f1);
            __nv_bfloat16 h2 = __float2bfloat16_rn(f2), h3 = __float2bfloat16_rn(f3);
            uint32_t hp0 = (uint32_t)*(uint16_t*)&h0 | ((uint32_t)*(uint16_t*)&h1 << 16);
            uint32_t hp1 = (uint32_t)*(uint16_t*)&h2 | ((uint32_t)*(uint16_t*)&h3 << 16);
            uint32_t lp0 = pack_bf16(f0 - __bfloat162float(h0), f1 - __bfloat162float(h1));
            uint32_t lp1 = pack_bf16(f2 - __bfloat162float(h2), f3 - __bfloat162float(h3));
            size_t base = (size_t)k * 64 + 2 * lane;
            yh32[base] = hp0; yh32[base + 1] = hp1;
            yl32[base] = lp0; yl32[base + 1] = lp1;
            if (lane == 0) {
                float ry = 1.f / fmaxf(1.f - s, 1e-12f);
                g_cc[k] = make_float4(s, ry, fb[k], 0.f);
            }
        }

        // ---- grid barrier (all 148 blocks co-resident: 1 CTA/SM) ----
        __threadfence();
        __syncthreads();
        if (tid == 0) {
            atomicAdd(&g_barA, 1u);
            while (*(volatile unsigned*)&g_barA < gridDim.x) {}
            __threadfence();
        }
        __syncthreads();
    }

    // =================== phase 1: GEMM + fused epilogue =====================
    const int NT = K >> 7;
    const int total = (NROW >> 7) * NT;
    const int base = total / (int)gridDim.x;
    const int extra = total - base * (int)gridDim.x;
    int t = (int)blockIdx.x * base + min((int)blockIdx.x, extra);
    const int tend = t + base + ((int)blockIdx.x < extra ? 1 : 0);

    const float T = __ldg(temp);
    const float nit2 = -1.f / (T * T);
    const float c2 = nit2 * 0.4804530139182014f;   // nit2 * ln(2)^2

#if TC_OK
    if (w == 0) tm_alloc(sb + SM_TMEMPTR, 512);
    __syncthreads();
    uint32_t tbase;
    asm volatile("ld.shared.b32 %0, [%1];" : "=r"(tbase) : "r"(sb + SM_TMEMPTR));

    float* x2a = (float*)(smem + SM_SXR);
    float* rxa = x2a + 128;
    const bool kfast = (K == 32000);

    // consumer-group identity
    const int grp = w >> 3;                        // 0: even tiles, 1: odd tiles
    const int ww  = w & 7;
    const int sp  = ww & 3;                        // TMEM subpartition = code group
    const int ch  = ww >> 2;                       // col half (64 cols)
    const int ltid = tid & 255;

    // hoisted swizzled dst offsets (8; +32768 gives the lo half)
    uint32_t foff[8];
    if (w < 16) {
        #pragma unroll
        for (int k = 0; k < 8; k++) {
            int idx = ltid + 256 * k;
            foff[k] = tile_off((idx & 2047) >> 4, idx & 15);
        }
    }

    while (t < tend) {
        const int m  = t / NT;
        const int n0 = t % NT;
        const int L  = min(tend, (m + 1) * NT) - t;

        // ---- segment init: fresh mbarriers + row-const tables ----
        __syncthreads();
        if (tid == 0) {
            #pragma unroll
            for (int s = 0; s < 4; s++) {
                mbar_init(FULLB(s), 1);
                mbar_init(EBB(s), NGRP);
            }
            mbar_init(BFB(0), NGRP);
            mbar_init(BFB(1), NGRP);
        }
        if (tid < 128) {
            x2a[tid] = g_x2[(m << 7) + tid];
            rxa[tid] = g_rx[(m << 7) + tid];
        }
        __syncthreads();

        if (w == 16) {
            // =========== PRODUCER warp: issue MMAs only ===========
            if (lane == 0) {
                mbar_wait(BFB(0), 0);                     // A + Y0 in smem
                fence_async_shared();
                issue_tile(sb + SM_B, sb + SM_A, tbase);
                tm_commit(FULLB(0));
                for (int i = 1; i < L; i++) {
                    if (i >= 4)
                        mbar_wait(EBB(i & 3), (uint32_t)(((i - 4) >> 2) & 1));
                    mbar_wait(BFB(i & 1), (uint32_t)((i >> 1) & 1));
                    fence_async_shared();
                    issue_tile(sb + SM_B + (uint32_t)(i & 1) * 65536u,
                               sb + SM_A,
                               tbase + (uint32_t)(i & 3) * 128u);
                    tm_commit(FULLB(i & 3));
                }
            }
        } else {
            // ==== CONSUMER groups: group `grp` owns tiles j ≡ grp (mod 2) ====
            // prologue fills: group 0 -> A + Y0; group 1 -> Y1
            if (grp == 0) {
                fill_tile_grp(sb + SM_A, g_phi, g_plo, (m << 7) * DD, ltid, foff);
                fill_tile_grp(sb + SM_B, g_yhi, g_ylo, (n0 << 7) * DD, ltid, foff);
                cp_arrive(BFB(0));
            } else if (L > 1) {
                fill_tile_grp(sb + SM_B + 65536u, g_yhi, g_ylo,
                              ((n0 + 1) << 7) * DD, ltid, foff);
                cp_arrive(BFB(1));
            }

            const uint32_t bb = sb + SM_B + (uint32_t)grp * 65536u;
            for (int j = grp; j < L; j += 2) {
                const uint32_t slot = (uint32_t)(j & 3);
                const int code = ((n0 + j) << 7) + (sp << 5) + lane;
                const float4 q = __ldg(&g_cc[code]);    // y2, ry, fb
                mbar_wait(FULLB(slot), (uint32_t)((j >> 2) & 1));
                tm_fence_after();

                const uint32_t dbase = tbase + slot * 128u + (uint32_t)(ch << 6);
                uint32_t ra[16], rb[16];
                ldtm16(ra, dbase);

                // refill this group's Y buffer with tile j+2
                if (j + 2 < L) {
                    fill_tile_grp(bb, g_yhi, g_ylo,
                                  ((n0 + j + 2) << 7) * DD, ltid, foff);
                    cp_arrive(BFB(grp));
                }

                const uint64_t qx2 = pk2(q.x, q.x);
                const uint64_t qy2 = pk2(q.y, q.y);
                const float* xw = x2a + (ch << 6);
                const float* rw = rxa + (ch << 6);
                float* obase = out + (size_t)((m << 7) + (ch << 6)) * K + code;

                tm_waitld();
                ldtm16(rb, dbase + 16u);
                if (kfast) {
                    epi_block<32000>(ra, xw, rw, 0,  qx2, qy2, q.z, c2, obase, K);
                    tm_waitld();
                    ldtm16(ra, dbase + 32u);
                    epi_block<32000>(rb, xw, rw, 8,  qx2, qy2, q.z, c2, obase, K);
                    tm_waitld();
                    ldtm16(rb, dbase + 48u);
                    epi_block<32000>(ra, xw, rw, 16, qx2, qy2, q.z, c2, obase, K);
                    tm_waitld();
                    epi_block<32000>(rb, xw, rw, 24, qx2, qy2, q.z, c2, obase, K);
                } else {
                    epi_block<0>(ra, xw, rw, 0,  qx2, qy2, q.z, c2, obase, K);
                    tm_waitld();
                    ldtm16(ra, dbase + 32u);
                    epi_block<0>(rb, xw, rw, 8,  qx2, qy2, q.z, c2, obase, K);
                    tm_waitld();
                    ldtm16(rb, dbase + 48u);
                    epi_block<0>(ra, xw, rw, 16, qx2, qy2, q.z, c2, obase, K);
                    tm_waitld();
                    epi_block<0>(rb, xw, rw, 24, qx2, qy2, q.z, c2, obase, K);
                }
                mbar_arrive(EBB(slot));
            }
        }
        t += L;
    }
    __syncthreads();
    if (w == 0) tm_dealloc(tbase, 512);
#else
    // -------- fallback (plain sm_103 cubin; GB300 loads the sm_103a one) ----
    float* Af = (float*)(smem);            // Af[d][m]
    float* Bf = (float*)(smem + 65536);    // Bf[d][n]
    const int tn = tid & 15, tm = (tid >> 4) & 15;
    const bool active = tid < 256;
    int cur_m = -1;
    while (t < tend) {
        const int m = t / NT, n = t % NT;
        __syncthreads();
        if (m != cur_m) {
            for (int idx = tid; idx < 128 * 128; idx += NTHREADS) {
                int r = idx >> 7, d = idx & 127;
                size_t o = (size_t)((m << 7) + r) * DD + d;
                Af[d * 128 + r] = __bfloat162float(g_phi[o]) + __bfloat162float(g_plo[o]);
            }
            cur_m = m;
        }
        for (int idx = tid; idx < 128 * 128; idx += NTHREADS) {
            int r = idx >> 7, d = idx & 127;
            size_t o = (size_t)((n << 7) + r) * DD + d;
            Bf[d * 128 + r] = __bfloat162float(g_yhi[o]) + __bfloat162float(g_ylo[o]);
        }
        __syncthreads();
        if (active) {
            float acc[8][8];
            #pragma unroll
            for (int i = 0; i < 8; i++)
                #pragma unroll
                for (int j = 0; j < 8; j++) acc[i][j] = 0.f;
            for (int d = 0; d < 128; d++) {
                float av[8], bv[8];
                #pragma unroll
                for (int i = 0; i < 8; i++) av[i] = Af[d * 128 + tm * 8 + i];
                #pragma unroll
                for (int j = 0; j < 8; j++) bv[j] = Bf[d * 128 + tn * 8 + j];
                #pragma unroll
                for (int i = 0; i < 8; i++)
                    #pragma unroll
                    for (int j = 0; j < 8; j++) acc[i][j] = fmaf(av[i], bv[j], acc[i][j]);
            }
            #pragma unroll
            for (int i = 0; i < 8; i++) {
                int grow = (m << 7) + tm * 8 + i;
                float x2r = g_x2[grow], rxr = g_rx[grow];
                #pragma unroll
                for (int j = 0; j < 8; j++) {
                    int c = (n << 7) + tn * 8 + j;
                    float4 q = g_cc[c];
                    out[(size_t)grow * K + c] =
                        hd_logit(acc[i][j], x2r, rxr, q.x, q.y, q.z, nit2);
                }
            }
        }
        t++;
    }
#endif

    // ---- exit: last block resets the grid-barrier counters for replay ------
    if (tid == 0) {
        unsigned x = atomicAdd(&g_barB, 1u);
        if (x == gridDim.x - 1) {
            *(volatile unsigned*)&g_barA = 0;
            *(volatile unsigned*)&g_barB = 0;
            __threadfence();
        }
    }
}

// -------------------- launch -------------------------------------------------
extern "C" void kernel_launch(void* const* d_in, const int* in_sizes, int n_in,
                              void* d_out, int out_size) {
    const float* v     = (const float*)d_in[0];
    const float* codes = (const float*)d_in[1];
    const float* W     = (const float*)d_in[2];
    const float* b     = (const float*)d_in[3];
    const float* fb    = (const float*)d_in[4];
    const float* temp  = (const float*)d_in[5];

    const int D = in_sizes[3];            // 128
    const int N = in_sizes[0] / D;        // 2048
    const int K = in_sizes[4];            // 32000

    cudaFuncSetAttribute(hd_fused, cudaFuncAttributeMaxDynamicSharedMemorySize,
                         SM_TOTAL);
    hd_fused<<<148, NTHREADS, SM_TOTAL>>>(v, codes, W, b, fb, temp,
                                          (float*)d_out, N, K);
}

// round 17
// speedup vs baseline: 1.1371x; 1.0148x over previous
#include <cuda_runtime.h>
#include <cuda_bf16.h>
#include <cstdint>

#define DD 128
#define NTHREADS 800            // 24 consumer warps (3 groups of 8) + 1 producer
#define NGRP 256                // threads per consumer group

#if defined(__CUDA_ARCH__) && defined(__CUDA_ARCH_FEAT_SM103_ALL)
#define TC_OK 1
#else
#define TC_OK 0
#endif

// -------------------- device scratch (no allocations allowed) ---------------
__device__ float g_x2[4096];
__device__ float g_rx[4096];
__device__ float4 g_cc[32768];            // per-code {y2, 1/(1-y2), fb, 0}
__device__ __nv_bfloat16 g_phi[4096 * DD];
__device__ __nv_bfloat16 g_plo[4096 * DD];
__device__ __nv_bfloat16 g_yhi[32768 * DD];
__device__ __nv_bfloat16 g_ylo[32768 * DD];
__device__ unsigned g_barA;
__device__ unsigned g_barB;

// -------------------- small helpers ----------------------------------------
__device__ __forceinline__ float wsum(float v) {
    #pragma unroll
    for (int o = 16; o > 0; o >>= 1) v += __shfl_xor_sync(0xffffffffu, v, o);
    return v;
}

__device__ __forceinline__ uint32_t s2u(const void* p) {
    uint32_t a;
    asm("{ .reg .u64 t; cvta.to.shared.u64 t, %1; cvt.u32.u64 %0, t; }"
        : "=r"(a) : "l"(p));
    return a;
}

__device__ __forceinline__ void cpasync16(uint32_t dst, const void* src) {
    asm volatile("cp.async.cg.shared.global [%0], [%1], 16;" :: "r"(dst), "l"(src));
}

__device__ __forceinline__ void mbar_init(uint32_t a, uint32_t cnt) {
    asm volatile("mbarrier.init.shared.b64 [%0], %1;" :: "r"(a), "r"(cnt) : "memory");
}
// HW-sleep wait (suspend-time hint -> no issue-slot burn while waiting)
__device__ __forceinline__ void mbar_wait(uint32_t a, uint32_t parity) {
    asm volatile(
        "{\n\t.reg .pred P;\n"
        "W%=:\n\t"
        "mbarrier.try_wait.parity.acquire.cta.shared::cta.b64 P, [%0], %1, 0x989680;\n\t"
        "@!P bra W%=;\n\t}"
        :: "r"(a), "r"(parity) : "memory");
}
__device__ __forceinline__ void mbar_arrive(uint32_t a) {
    asm volatile("mbarrier.arrive.shared.b64 _, [%0];" :: "r"(a) : "memory");
}
__device__ __forceinline__ void cp_arrive(uint32_t a) {
    asm volatile("cp.async.mbarrier.arrive.noinc.shared.b64 [%0];"
                 :: "r"(a) : "memory");
}
__device__ __forceinline__ float sqrt_approx(float x) {
    float r;
    asm("sqrt.approx.f32 %0, %1;" : "=f"(r) : "f"(x));
    return r;
}

// -------------------- packed f32x2 ops (Blackwell) ---------------------------
__device__ __forceinline__ uint64_t pk2(float lo, float hi) {
    uint64_t r;
    asm("mov.b64 %0, {%1, %2};" : "=l"(r) : "f"(lo), "f"(hi));
    return r;
}
__device__ __forceinline__ void unpk2(uint64_t v, float& lo, float& hi) {
    asm("mov.b64 {%0, %1}, %2;" : "=f"(lo), "=f"(hi) : "l"(v));
}
__device__ __forceinline__ uint64_t add2(uint64_t a, uint64_t b) {
    uint64_t r; asm("add.rn.f32x2 %0, %1, %2;" : "=l"(r) : "l"(a), "l"(b)); return r;
}
__device__ __forceinline__ uint64_t mul2(uint64_t a, uint64_t b) {
    uint64_t r; asm("mul.rn.f32x2 %0, %1, %2;" : "=l"(r) : "l"(a), "l"(b)); return r;
}
__device__ __forceinline__ uint64_t fma2v(uint64_t a, uint64_t b, uint64_t c) {
    uint64_t r; asm("fma.rn.f32x2 %0, %1, %2, %3;" : "=l"(r) : "l"(a), "l"(b), "l"(c)); return r;
}

#if TC_OK
__device__ __forceinline__ void tm_alloc(uint32_t smem_res, uint32_t ncols) {
    asm volatile("tcgen05.alloc.cta_group::1.sync.aligned.shared::cta.b32 [%0], %1;"
                 :: "r"(smem_res), "r"(ncols) : "memory");
}
__device__ __forceinline__ void tm_dealloc(uint32_t tmem, uint32_t ncols) {
    asm volatile("tcgen05.dealloc.cta_group::1.sync.aligned.b32 %0, %1;" :: "r"(tmem), "r"(ncols));
}
__device__ __forceinline__ void tm_commit(uint32_t mbar) {
    asm volatile("tcgen05.commit.cta_group::1.mbarrier::arrive::one.shared::cluster.b64 [%0];"
                 :: "r"(mbar) : "memory");
}
__device__ __forceinline__ void tm_fence_after() {
    asm volatile("tcgen05.fence::after_thread_sync;" ::: "memory");
}
__device__ __forceinline__ void fence_async_shared() {
    asm volatile("fence.proxy.async.shared::cta;" ::: "memory");
}
__device__ __forceinline__ void tm_waitld() {
    asm volatile("tcgen05.wait::ld.sync.aligned;" ::: "memory");
}
__device__ __forceinline__ void ldtm16(uint32_t* r, uint32_t a) {
    asm volatile("tcgen05.ld.sync.aligned.32x32b.x16.b32 "
                 "{%0,%1,%2,%3,%4,%5,%6,%7,%8,%9,%10,%11,%12,%13,%14,%15}, [%16];"
                 : "=r"(r[0]), "=r"(r[1]), "=r"(r[2]),  "=r"(r[3]),
                   "=r"(r[4]), "=r"(r[5]), "=r"(r[6]),  "=r"(r[7]),
                   "=r"(r[8]), "=r"(r[9]), "=r"(r[10]), "=r"(r[11]),
                   "=r"(r[12]), "=r"(r[13]), "=r"(r[14]), "=r"(r[15])
                 : "r"(a));
}

// SS bf16 MMA, cg1, fp32 accumulate. M=128, N=128.
#define IDESC_BF16_128x128 ((1u<<4)|(1u<<7)|(1u<<10)|((128u/8u)<<17)|((128u/16u)<<24))

__device__ __forceinline__ void mma_ss(uint32_t d, uint64_t a, uint64_t b,
                                       uint32_t en) {
    asm volatile(
        "{\n\t.reg .pred p;\n\t"
        "setp.ne.u32 p, %5, 0;\n\t"
        "tcgen05.mma.cta_group::1.kind::f16 [%0], %1, %2, %3, {%4, %4, %4, %4}, p;\n\t}"
        :: "r"(d), "l"(a), "l"(b), "r"(IDESC_BF16_128x128), "r"(0u), "r"(en)
        : "memory");
}
#endif  // TC_OK

// 64-bit SMEM descriptor: SW128, version 1 (Blackwell), SBO=64, LBO=1
__device__ __forceinline__ uint64_t mkdesc(uint32_t addr) {
    return ((uint64_t)2 << 61) | ((uint64_t)1 << 46) | ((uint64_t)64 << 32)
         | ((uint64_t)1 << 16) | (uint64_t)((addr >> 4) & 0x3FFFu);
}

// Atom-blocked SW128 offset for a 128-row x 128-col bf16 tile.
__device__ __forceinline__ uint32_t tile_off(int r, int g) {
    uint32_t lin = (uint32_t)((r >> 3) + ((g >> 3) << 4)) * 1024u
                 + (uint32_t)(r & 7) * 128u + (uint32_t)(g & 7) * 16u;
    return lin ^ ((lin >> 3) & 0x70u);
}

// -------------------- smem layout --------------------------------------------
#define SM_TMEMPTR 0
#define SM_MBAR    8                             // 10 mbars x 8B
#define SM_A       1024                          // P: hi 32KB + lo 32KB
#define SM_B       (SM_A + 65536)                // Y: 2 x (hi 32KB + lo 32KB); W^T in prep
#define SM_SXR     (SM_B + 131072)               // x2[128] floats, rx[128] floats
#define SM_TOTAL   (SM_SXR + 1024)

#define FULLB(s) (sb + SM_MBAR + (uint32_t)(s) * 8u)
#define EBB(s)   (sb + SM_MBAR + 32u + (uint32_t)(s) * 8u)
#define BFB(b)   (sb + SM_MBAR + 64u + (uint32_t)(b) * 8u)

#if TC_OK
// A = Y (sa_y), B = P (sb_p): D[code, row]
__device__ __forceinline__ void issue_tile(uint32_t sa_y, uint32_t sb_p, uint32_t d) {
    uint64_t ah = mkdesc(sa_y), al = mkdesc(sa_y + 32768u);
    uint64_t bh = mkdesc(sb_p), bl = mkdesc(sb_p + 32768u);
    #pragma unroll
    for (int kk = 0; kk < 8; kk++) {
        uint32_t off = (uint32_t)(kk >> 2) * 1024u + (uint32_t)(kk & 3) * 2u;
        mma_ss(d, ah + off, bh + off, kk > 0 ? 1u : 0u);
        mma_ss(d, ah + off, bl + off, 1u);
        mma_ss(d, al + off, bh + off, 1u);
    }
}

// group fill: one full hi+lo tile by 256 threads; foff = 8 hoisted offsets
__device__ __forceinline__ void fill_tile_grp(uint32_t dst,
                                              const __nv_bfloat16* __restrict__ hi,
                                              const __nv_bfloat16* __restrict__ lo,
                                              int rowelem, int ltid,
                                              const uint32_t* foff) {
    #pragma unroll
    for (int k = 0; k < 8; k++) {
        int src = rowelem + 8 * ltid + 2048 * k;
        cpasync16(dst + foff[k], hi + src);
        cpasync16(dst + foff[k] + 32768u, lo + src);
    }
}

// packed epilogue for 8 element-pairs (16 rows) from one ldtm16 chunk.
template<int KC>
__device__ __forceinline__ void epi_block(const uint32_t* __restrict__ r,
                                          const float* __restrict__ x2a,
                                          const float* __restrict__ rxa,
                                          int pbase,
                                          uint64_t qx2, uint64_t qy2,
                                          float qz, float c2,
                                          float* __restrict__ obase, int Krt) {
    const uint64_t NEG2  = pk2(-2.f, -2.f);
    const uint64_t ONE2  = pk2(1.f, 1.f);
    const uint64_t MONE2 = pk2(-1.f, -1.f);
    #pragma unroll
    for (int p = 0; p < 8; p++) {
        const int pp = pbase + p;
        float2 x2p = *(const float2*)(x2a + 2 * pp);
        float2 rxp = *(const float2*)(rxa + 2 * pp);
        uint64_t xv2 = pk2(__uint_as_float(r[2 * p]), __uint_as_float(r[2 * p + 1]));
        uint64_t s2  = add2(pk2(x2p.x, x2p.y), qx2);
        uint64_t u2  = fma2v(xv2, NEG2, s2);
        float u0, u1; unpk2(u2, u0, u1);
        u0 = fmaxf(u0, 0.f); u1 = fmaxf(u1, 0.f);
        uint64_t rr2 = mul2(pk2(rxp.x, rxp.y), qy2);
        uint64_t t2  = fma2v(pk2(u0, u1), rr2, ONE2);
        uint64_t a2  = fma2v(t2, t2, MONE2);
        float t0, t1; unpk2(t2, t0, t1);
        float a0, a1; unpk2(a2, a0, a1);
        float w0 = sqrt_approx(a0), w1 = sqrt_approx(a1);
        float l0 = __log2f(t0 + w0), l1 = __log2f(t1 + w1);
        float res0 = fmaf(l0 * l0, c2, qz);
        float res1 = fmaf(l1 * l1, c2, qz);
        if (KC > 0) {
            __stcs(obase + (size_t)(2 * pp) * KC, res0);
            __stcs(obase + (size_t)(2 * pp + 1) * KC, res1);
        } else {
            __stcs(obase + (size_t)(2 * pp) * Krt, res0);
            __stcs(obase + (size_t)(2 * pp + 1) * Krt, res1);
        }
    }
}
#endif

__device__ __forceinline__ float hd_logit(float xv, float x2r, float rxr,
                                          float y2c, float ryc, float fbc,
                                          float nit2) {
    float u = fmaxf(fmaf(-2.f, xv, x2r + y2c), 0.f);
    float t = fmaf(u, rxr * ryc, 1.f);
    float a = fmaf(t, t, -1.f);
    float w = sqrt_approx(a);
    float l = __logf(t + w);
    return fmaf(l * l, nit2, fbc);
}

__device__ __forceinline__ uint32_t pack_bf16(float a, float b) {
    __nv_bfloat16 ha = __float2bfloat16_rn(a), hb = __float2bfloat16_rn(b);
    uint16_t ua = *(uint16_t*)&ha, ub = *(uint16_t*)&hb;
    return (uint32_t)ua | ((uint32_t)ub << 16);
}

// ======================= the single fused kernel =============================
__global__ void __launch_bounds__(NTHREADS, 1)
hd_fused(const float* __restrict__ V, const float* __restrict__ Y,
         const float* __restrict__ W, const float* __restrict__ bvec,
         const float* __restrict__ fb, const float* __restrict__ temp,
         float* __restrict__ out, int NROW, int K) {
    extern __shared__ char smem[];
    uint32_t sb = s2u(smem);
    int tid = threadIdx.x, w = tid >> 5, lane = tid & 31;

    // =================== phase 0: prep (rows + codes) =======================
    {
        const int nrowblk = (NROW + 15) >> 4;        // 16 rows per block
        if ((int)blockIdx.x < nrowblk) {
            float* sWt = (float*)(smem + SM_B);
            for (int idx = tid; idx < DD * DD; idx += NTHREADS) {
                int d = idx >> 7, e = idx & 127;
                sWt[e * 132 + d] = W[idx];
            }
            __syncthreads();
            int row = ((int)blockIdx.x << 4) + w;
            if (w < 16 && row < NROW) {
                const float* v = V + (size_t)row * DD;
                float vq[4];
                #pragma unroll
                for (int q = 0; q < 4; q++) vq[q] = v[lane + 32 * q];
                float n2 = wsum(vq[0]*vq[0] + vq[1]*vq[1] + vq[2]*vq[2] + vq[3]*vq[3]);
                float n  = sqrtf(fmaxf(n2, 1e-30f));
                float xn = tanhf(n);
                float s0 = xn / n;
                float p0[4];
                #pragma unroll
                for (int q = 0; q < 4; q++) p0[q] = s0 * vq[q];

                float mq[4] = {0.f, 0.f, 0.f, 0.f};
                #pragma unroll
                for (int e = 0; e < DD; e++) {
                    float pe = __shfl_sync(0xffffffffu, p0[e >> 5], e & 31);
                    #pragma unroll
                    for (int q = 0; q < 4; q++)
                        mq[q] = fmaf(pe, sWt[e * 132 + 32 * q + lane], mq[q]);
                }
                float mxn2 = wsum(mq[0]*mq[0] + mq[1]*mq[1] + mq[2]*mq[2] + mq[3]*mq[3]);
                float mxn  = sqrtf(fmaxf(mxn2, 1e-30f));
                float xc   = fminf(xn, 1.f - 1e-5f);
                float ath  = 0.5f * __logf((1.f + xc) / (1.f - xc));
                float g    = tanhf(mxn / fmaxf(xn, 1e-15f) * ath) / mxn;
                float rq[4];
                #pragma unroll
                for (int q = 0; q < 4; q++) rq[q] = g * mq[q];

                float bq[4];
                #pragma unroll
                for (int q = 0; q < 4; q++) bq[q] = bvec[lane + 32 * q];
                float bn2 = wsum(bq[0]*bq[0] + bq[1]*bq[1] + bq[2]*bq[2] + bq[3]*bq[3]);
                float bn  = sqrtf(fmaxf(bn2, 1e-30f));
                float tb  = tanhf(bn);
                float sb2 = tb / bn;
                float ebq[4];
                #pragma unroll
                for (int q = 0; q < 4; q++) ebq[q] = sb2 * bq[q];
                float y2 = tb * tb;

                float x2 = wsum(rq[0]*rq[0] + rq[1]*rq[1] + rq[2]*rq[2] + rq[3]*rq[3]);
                float xy = wsum(rq[0]*ebq[0] + rq[1]*ebq[1] + rq[2]*ebq[2] + rq[3]*ebq[3]);
                float ca  = 1.f + 2.f * xy + y2;
                float cb  = 1.f - x2;
                float den = fmaxf(1.f + 2.f * xy + x2 * y2, 1e-15f);
                float inv = 1.f / den;
                float pq[4], ps = 0.f;
                #pragma unroll
                for (int q = 0; q < 4; q++) {
                    pq[q] = (ca * rq[q] + cb * ebq[q]) * inv;
                    ps = fmaf(pq[q], pq[q], ps);
                }
                float px2 = wsum(ps);
                #pragma unroll
                for (int q = 0; q < 4; q++) {
                    int d = lane + 32 * q;
                    __nv_bfloat16 hi = __float2bfloat16_rn(pq[q]);
                    __nv_bfloat16 lo = __float2bfloat16_rn(pq[q] - __bfloat162float(hi));
                    g_phi[(size_t)row * DD + d] = hi;
                    g_plo[(size_t)row * DD + d] = lo;
                }
                if (lane == 0) {
                    g_x2[row] = px2;
                    g_rx[row] = 2.f / fmaxf(1.f - px2, 1e-12f);
                }
            }
        }

        // codes: global-warp strided, float4 loads, packed bf16x2 stores
        const int gw  = (int)blockIdx.x * 25 + w;
        const int gws = (int)gridDim.x * 25;
        uint32_t* yh32 = (uint32_t*)g_yhi;
        uint32_t* yl32 = (uint32_t*)g_ylo;
        for (int k = gw; k < K; k += gws) {
            const float4 yv = ((const float4*)(Y + (size_t)k * DD))[lane];
            float s = wsum(fmaf(yv.x, yv.x, fmaf(yv.y, yv.y,
                          fmaf(yv.z, yv.z, yv.w * yv.w))));
            float f0 = yv.x, f1 = yv.y, f2 = yv.z, f3 = yv.w;
            __nv_bfloat16 h0 = __float2bfloat16_rn(f0), h1 = __float2bfloat16_rn(f1);
            __nv_bfloat16 h2 = __float2bfloat16_rn(f2), h3 = __float2bfloat16_rn(f3);
            uint32_t hp0 = (uint32_t)*(uint16_t*)&h0 | ((uint32_t)*(uint16_t*)&h1 << 16);
            uint32_t hp1 = (uint32_t)*(uint16_t*)&h2 | ((uint32_t)*(uint16_t*)&h3 << 16);
            uint32_t lp0 = pack_bf16(f0 - __bfloat162float(h0), f1 - __bfloat162float(h1));
            uint32_t lp1 = pack_bf16(f2 - __bfloat162float(h2), f3 - __bfloat162float(h3));
            size_t base = (size_t)k * 64 + 2 * lane;
            yh32[base] = hp0; yh32[base + 1] = hp1;
            yl32[base] = lp0; yl32[base + 1] = lp1;
            if (lane == 0) {
                float ry = 1.f / fmaxf(1.f - s, 1e-12f);
                g_cc[k] = make_float4(s, ry, fb[k], 0.f);
            }
        }

        // ---- grid barrier (all 148 blocks co-resident: 1 CTA/SM) ----
        __threadfence();
        __syncthreads();
        if (tid == 0) {
            atomicAdd(&g_barA, 1u);
            while (*(volatile unsigned*)&g_barA < gridDim.x) {}
            __threadfence();
        }
        __syncthreads();
    }

    // =================== phase 1: GEMM + fused epilogue =====================
    const int NT = K >> 7;
    const int total = (NROW >> 7) * NT;
    const int base = total / (int)gridDim.x;
    const int extra = total - base * (int)gridDim.x;
    int t = (int)blockIdx.x * base + min((int)blockIdx.x, extra);
    const int tend = t + base + ((int)blockIdx.x < extra ? 1 : 0);

    const float T = __ldg(temp);
    const float nit2 = -1.f / (T * T);
    const float c2 = nit2 * 0.4804530139182014f;   // nit2 * ln(2)^2

#if TC_OK
    if (w == 0) tm_alloc(sb + SM_TMEMPTR, 512);
    __syncthreads();
    uint32_t tbase;
    asm volatile("ld.shared.b32 %0, [%1];" : "=r"(tbase) : "r"(sb + SM_TMEMPTR));

    float* x2a = (float*)(smem + SM_SXR);
    float* rxa = x2a + 128;
    const bool kfast = (K == 32000);

    // consumer-group identity: 3 groups of 8 warps, tiles j ≡ grp (mod 3)
    const int grp = w >> 3;                        // 0,1,2 (w<24); producer w==24
    const int ww  = w & 7;
    const int sp  = ww & 3;                        // TMEM subpartition = code group
    const int ch  = ww >> 2;                       // col half (64 cols)
    const int ltid = tid & 255;

    // hoisted swizzled dst offsets (8; +32768 gives the lo half)
    uint32_t foff[8];
    if (w < 24) {
        #pragma unroll
        for (int k = 0; k < 8; k++) {
            int idx = ltid + 256 * k;
            foff[k] = tile_off((idx & 2047) >> 4, idx & 15);
        }
    }

    while (t < tend) {
        const int m  = t / NT;
        const int n0 = t % NT;
        const int L  = min(tend, (m + 1) * NT) - t;

        // ---- segment init: fresh mbarriers + row-const tables ----
        __syncthreads();
        if (tid == 0) {
            #pragma unroll
            for (int s = 0; s < 4; s++) {
                mbar_init(FULLB(s), 1);
                mbar_init(EBB(s), NGRP);
            }
            mbar_init(BFB(0), NGRP);
            mbar_init(BFB(1), NGRP);
        }
        if (tid < 128) {
            x2a[tid] = g_x2[(m << 7) + tid];
            rxa[tid] = g_rx[(m << 7) + tid];
        }
        __syncthreads();

        if (w == 24) {
            // =========== PRODUCER warp: issue MMAs only ===========
            if (lane == 0) {
                mbar_wait(BFB(0), 0);                     // A + Y0 in smem
                fence_async_shared();
                issue_tile(sb + SM_B, sb + SM_A, tbase);
                tm_commit(FULLB(0));
                for (int i = 1; i < L; i++) {
                    if (i >= 4)
                        mbar_wait(EBB(i & 3), (uint32_t)(((i - 4) >> 2) & 1));
                    mbar_wait(BFB(i & 1), (uint32_t)((i >> 1) & 1));
                    fence_async_shared();
                    issue_tile(sb + SM_B + (uint32_t)(i & 1) * 65536u,
                               sb + SM_A,
                               tbase + (uint32_t)(i & 3) * 128u);
                    tm_commit(FULLB(i & 3));
                }
            }
        } else {
            // ==== CONSUMER groups: group `grp` owns tiles j ≡ grp (mod 3) ====
            // prologue fills: group 0 -> A + Y0; group 1 -> Y1; group 2 -> none
            if (grp == 0) {
                fill_tile_grp(sb + SM_A, g_phi, g_plo, (m << 7) * DD, ltid, foff);
                fill_tile_grp(sb + SM_B, g_yhi, g_ylo, (n0 << 7) * DD, ltid, foff);
                cp_arrive(BFB(0));
            } else if (grp == 1 && L > 1) {
                fill_tile_grp(sb + SM_B + 65536u, g_yhi, g_ylo,
                              ((n0 + 1) << 7) * DD, ltid, foff);
                cp_arrive(BFB(1));
            }

            for (int j = grp; j < L; j += 3) {
                const uint32_t slot = (uint32_t)(j & 3);
                const int code = ((n0 + j) << 7) + (sp << 5) + lane;
                const float4 q = __ldg(&g_cc[code]);    // y2, ry, fb
                mbar_wait(FULLB(slot), (uint32_t)((j >> 2) & 1));
                tm_fence_after();

                const uint32_t dbase = tbase + slot * 128u + (uint32_t)(ch << 6);
                uint32_t ra[16], rb[16];
                ldtm16(ra, dbase);

                // refill the Y buffer MMA(j) just released with tile j+2's Y
                if (j + 2 < L) {
                    fill_tile_grp(sb + SM_B + (uint32_t)(j & 1) * 65536u,
                                  g_yhi, g_ylo, ((n0 + j + 2) << 7) * DD,
                                  ltid, foff);
                    cp_arrive(BFB(j & 1));
                }

                const uint64_t qx2 = pk2(q.x, q.x);
                const uint64_t qy2 = pk2(q.y, q.y);
                const float* xw = x2a + (ch << 6);
                const float* rw = rxa + (ch << 6);
                float* obase = out + (size_t)((m << 7) + (ch << 6)) * K + code;

                tm_waitld();
                ldtm16(rb, dbase + 16u);
                if (kfast) {
                    epi_block<32000>(ra, xw, rw, 0,  qx2, qy2, q.z, c2, obase, K);
                    tm_waitld();
                    ldtm16(ra, dbase + 32u);
                    epi_block<32000>(rb, xw, rw, 8,  qx2, qy2, q.z, c2, obase, K);
                    tm_waitld();
                    ldtm16(rb, dbase + 48u);
                    epi_block<32000>(ra, xw, rw, 16, qx2, qy2, q.z, c2, obase, K);
                    tm_waitld();
                    epi_block<32000>(rb, xw, rw, 24, qx2, qy2, q.z, c2, obase, K);
                } else {
                    epi_block<0>(ra, xw, rw, 0,  qx2, qy2, q.z, c2, obase, K);
                    tm_waitld();
                    ldtm16(ra, dbase + 32u);
                    epi_block<0>(rb, xw, rw, 8,  qx2, qy2, q.z, c2, obase, K);
                    tm_waitld();
                    ldtm16(rb, dbase + 48u);
                    epi_block<0>(ra, xw, rw, 16, qx2, qy2, q.z, c2, obase, K);
                    tm_waitld();
                    epi_block<0>(rb, xw, rw, 24, qx2, qy2, q.z, c2, obase, K);
                }
                mbar_arrive(EBB(slot));
            }
        }
        t += L;
    }
    __syncthreads();
    if (w == 0) tm_dealloc(tbase, 512);
#else
    // -------- fallback (plain sm_103 cubin; GB300 loads the sm_103a one) ----
    float* Af = (float*)(smem);            // Af[d][m]
    float* Bf = (float*)(smem + 65536);    // Bf[d][n]
    const int tn = tid & 15, tm = (tid >> 4) & 15;
    const bool active = tid < 256;
    int cur_m = -1;
    while (t < tend) {
        const int m = t / NT, n = t % NT;
        __syncthreads();
        if (m != cur_m) {
            for (int idx = tid; idx < 128 * 128; idx += NTHREADS) {
                int r = idx >> 7, d = idx & 127;
                size_t o = (size_t)((m << 7) + r) * DD + d;
                Af[d * 128 + r] = __bfloat162float(g_phi[o]) + __bfloat162float(g_plo[o]);
            }
            cur_m = m;
        }
        for (int idx = tid; idx < 128 * 128; idx += NTHREADS) {
            int r = idx >> 7, d = idx & 127;
            size_t o = (size_t)((n << 7) + r) * DD + d;
            Bf[d * 128 + r] = __bfloat162float(g_yhi[o]) + __bfloat162float(g_ylo[o]);
        }
        __syncthreads();
        if (active) {
            float acc[8][8];
            #pragma unroll
            for (int i = 0; i < 8; i++)
                #pragma unroll
                for (int j = 0; j < 8; j++) acc[i][j] = 0.f;
            for (int d = 0; d < 128; d++) {
                float av[8], bv[8];
                #pragma unroll
                for (int i = 0; i < 8; i++) av[i] = Af[d * 128 + tm * 8 + i];
                #pragma unroll
                for (int j = 0; j < 8; j++) bv[j] = Bf[d * 128 + tn * 8 + j];
                #pragma unroll
                for (int i = 0; i < 8; i++)
                    #pragma unroll
                    for (int j = 0; j < 8; j++) acc[i][j] = fmaf(av[i], bv[j], acc[i][j]);
            }
            #pragma unroll
            for (int i = 0; i < 8; i++) {
                int grow = (m << 7) + tm * 8 + i;
                float x2r = g_x2[grow], rxr = g_rx[grow];
                #pragma unroll
                for (int j = 0; j < 8; j++) {
                    int c = (n << 7) + tn * 8 + j;
                    float4 q = g_cc[c];
                    out[(size_t)grow * K + c] =
                        hd_logit(acc[i][j], x2r, rxr, q.x, q.y, q.z, nit2);
                }
            }
        }
        t++;
    }
#endif

    // ---- exit: last block resets the grid-barrier counters for replay ------
    if (tid == 0) {
        unsigned x = atomicAdd(&g_barB, 1u);
        if (x == gridDim.x - 1) {
            *(volatile unsigned*)&g_barA = 0;
            *(volatile unsigned*)&g_barB = 0;
            __threadfence();
        }
    }
}

// -------------------- launch -------------------------------------------------
extern "C" void kernel_launch(void* const* d_in, const int* in_sizes, int n_in,
                              void* d_out, int out_size) {
    const float* v     = (const float*)d_in[0];
    const float* codes = (const float*)d_in[1];
    const float* W     = (const float*)d_in[2];
    const float* b     = (const float*)d_in[3];
    const float* fb    = (const float*)d_in[4];
    const float* temp  = (const float*)d_in[5];

    const int D = in_sizes[3];            // 128
    const int N = in_sizes[0] / D;        // 2048
    const int K = in_sizes[4];            // 32000

    cudaFuncSetAttribute(hd_fused, cudaFuncAttributeMaxDynamicSharedMemorySize,
                         SM_TOTAL);
    hd_fused<<<148, NTHREADS, SM_TOTAL>>>(v, codes, W, b, fb, temp,
                                          (float*)d_out, N, K);
}